// round 15
// baseline (speedup 1.0000x reference)
#include <cuda_runtime.h>
#include <cuda_bf16.h>
#include <cstdint>

#define Bb   2
#define Cc   512
#define Nn   2304          // 48*48
#define Gg   32
#define CG   16            // Cc/Gg
#define NH   8
#define DH   64
#define HID  512
#define QKVJ 1536
#define NKV  4
#define Ltot 2308          // Nn + NKV
#define Lpad 2368          // 37*64
#define KT2  64
#define NKT2 37
#define SCALE 0.125f       // DH^-0.5
#define OUT_NX 18          // Nn/128
#define OUT_NY 4           // HID/128

typedef unsigned long long u64;
typedef __nv_bfloat16 bf16;

// byte swizzle for 128-byte rows (mma smem tiles)
#define SW128B(o) ((o) ^ (((o) >> 3) & 0x70))

// ---------- mma.sync helpers ----------
__device__ __forceinline__ uint32_t smem_u32_of(const void* p) {
    uint32_t a;
    asm("{ .reg .u64 t; cvta.to.shared.u64 t, %1; cvt.u32.u64 %0, t; }" : "=r"(a) : "l"(p));
    return a;
}
__device__ __forceinline__ void ldm_x4(uint32_t r[4], uint32_t a) {
    asm volatile("ldmatrix.sync.aligned.m8n8.x4.shared.b16 {%0,%1,%2,%3}, [%4];"
        : "=r"(r[0]), "=r"(r[1]), "=r"(r[2]), "=r"(r[3]) : "r"(a));
}
__device__ __forceinline__ void ldm_x2(uint32_t r[2], uint32_t a) {
    asm volatile("ldmatrix.sync.aligned.m8n8.x2.shared.b16 {%0,%1}, [%2];"
        : "=r"(r[0]), "=r"(r[1]) : "r"(a));
}
__device__ __forceinline__ void mma_bf16(float d[4], const uint32_t a[4], const uint32_t b[2]) {
    asm volatile(
        "mma.sync.aligned.m16n8k16.row.col.f32.bf16.bf16.f32 "
        "{%0,%1,%2,%3}, {%4,%5,%6,%7}, {%8,%9}, {%0,%1,%2,%3};"
        : "+f"(d[0]), "+f"(d[1]), "+f"(d[2]), "+f"(d[3])
        : "r"(a[0]), "r"(a[1]), "r"(a[2]), "r"(a[3]), "r"(b[0]), "r"(b[1]));
}
__device__ __forceinline__ void cpa16(uint32_t s, const void* g) {
    asm volatile("cp.async.cg.shared.global [%0], [%1], 16;" :: "r"(s), "l"(g));
}
#define CP_COMMIT() asm volatile("cp.async.commit_group;" ::: "memory")
#define CP_WAIT0()  asm volatile("cp.async.wait_group 0;" ::: "memory")

// pack two floats to bf16x2 hi + residual lo
__device__ __forceinline__ void split2(float a, float b, uint32_t& hi, uint32_t& lo) {
    __nv_bfloat162 h, l2;
    h.x = __float2bfloat16(a); h.y = __float2bfloat16(b);
    l2.x = __float2bfloat16(a - __bfloat162float(h.x));
    l2.y = __float2bfloat16(b - __bfloat162float(h.y));
    hi = *(uint32_t*)&h; lo = *(uint32_t*)&l2;
}

// ------------------------- scratch (device globals) -------------------------
__device__ float d_s1[Bb*Cc], d_b1[Bb*Cc], d_s2[Bb*Cc], d_b2[Bb*Cc];
__device__ bf16 d_thi[(size_t)Bb*Nn*Cc],  d_tlo[(size_t)Bb*Nn*Cc];   // tokens [b][tok][c]
__device__ bf16 d_whi[(size_t)QKVJ*Cc],   d_wlo[(size_t)QKVJ*Cc];    // w_qkv  [j][c]
__device__ bf16 d_wohi[(size_t)Cc*HID],   d_wolo[(size_t)Cc*HID];    // w_out  [c][j]
__device__ bf16 d_qhi[(size_t)Bb*NH*Nn*DH],   d_qlo[(size_t)Bb*NH*Nn*DH];    // [b,h][tok][d] prescaled
__device__ bf16 d_khi[(size_t)Bb*NH*Lpad*DH], d_klo[(size_t)Bb*NH*Lpad*DH];  // [b,h][tok][d]
__device__ bf16 d_vhi[(size_t)Bb*NH*DH*Lpad], d_vlo[(size_t)Bb*NH*DH*Lpad];  // [b,h][d][tok]
__device__ bf16 d_ohi[(size_t)Bb*Nn*HID], d_olo[(size_t)Bb*Nn*HID];  // attn out [b][tok][j]
__device__ float d_y[(size_t)Bb*Cc*Nn];
__device__ float d_part[Bb*OUT_NY*OUT_NX*8*2];   // GN2 per-CTA group partials (sum, sumsq)

// ------------------------- GroupNorm stats -> affine (input GN) -------------------------
__global__ void gn_stats_kernel(const float* __restrict__ src,
                                const float* __restrict__ w,
                                const float* __restrict__ bgn,
                                float* __restrict__ sout,
                                float* __restrict__ bout) {
    int b = blockIdx.x >> 5;
    int g = blockIdx.x & 31;
    const float* p = src + ((size_t)b*Cc + g*CG) * Nn;
    float sum = 0.f, sq = 0.f;
    for (int i = threadIdx.x; i < CG*Nn; i += 256) {
        float v = p[i]; sum += v; sq += v*v;
    }
    __shared__ float r0[8], r1[8];
    __shared__ float smu, srs;
    int lane = threadIdx.x & 31, wid = threadIdx.x >> 5;
#pragma unroll
    for (int off = 16; off; off >>= 1) {
        sum += __shfl_xor_sync(~0u, sum, off);
        sq  += __shfl_xor_sync(~0u, sq,  off);
    }
    if (!lane) { r0[wid] = sum; r1[wid] = sq; }
    __syncthreads();
    if (threadIdx.x == 0) {
        float s = 0.f, q = 0.f;
#pragma unroll
        for (int i = 0; i < 8; i++) { s += r0[i]; q += r1[i]; }
        float inv = 1.f / (float)(CG*Nn);
        float mu  = s * inv;
        float var = q * inv - mu*mu;
        smu = mu; srs = rsqrtf(var + 1e-5f);
    }
    __syncthreads();
    if (threadIdx.x < CG) {
        int c = g*CG + threadIdx.x;
        float ww = w[c];
        float sc = srs * ww;
        sout[b*Cc + c] = sc;
        bout[b*Cc + c] = bgn[c] - smu * sc;
    }
}

// ------------------------- prep: transpose x + GN1 affine + bf16 split -------------------------
__global__ void prep_x_kernel(const float* __restrict__ x) {
    __shared__ float t[32][33];
    int b = blockIdx.z;
    int c0 = blockIdx.y * 32;
    int t0 = blockIdx.x * 32;
    int lx = threadIdx.x & 31, ly = threadIdx.x >> 5;
#pragma unroll
    for (int i = 0; i < 4; i++) {
        int c = c0 + ly + i*8;
        float v = x[((size_t)b*Cc + c)*Nn + t0 + lx];
        t[ly + i*8][lx] = v * d_s1[b*Cc + c] + d_b1[b*Cc + c];
    }
    __syncthreads();
#pragma unroll
    for (int i = 0; i < 4; i++) {
        int tok = t0 + ly + i*8;
        int c = c0 + lx;
        float v = t[lx][ly + i*8];
        bf16 hi = __float2bfloat16(v);
        bf16 lo = __float2bfloat16(v - __bfloat162float(hi));
        size_t idx = ((size_t)b*Nn + tok)*Cc + c;
        d_thi[idx] = hi; d_tlo[idx] = lo;
    }
}

// ------------------------- prep: split both weight matrices (one launch) -------------------------
#define SPLIT1_BLOCKS ((QKVJ*Cc)/256)
__global__ void split_both_kernel(const float* __restrict__ w_qkv,
                                  const float* __restrict__ w_out) {
    int blk = blockIdx.x;
    const float* src; bf16 *hi, *lo; int i;
    if (blk < SPLIT1_BLOCKS) {
        src = w_qkv; hi = d_whi; lo = d_wlo;
        i = blk * 256 + threadIdx.x;
    } else {
        src = w_out; hi = d_wohi; lo = d_wolo;
        i = (blk - SPLIT1_BLOCKS) * 256 + threadIdx.x;
    }
    float v = src[i];
    bf16 h = __float2bfloat16(v);
    hi[i] = h;
    lo[i] = __float2bfloat16(v - __bfloat162float(h));
}

// ------------------------- memory kv prepend + zero pad (coalesced, wide grid) -------------------------
#define PADT (Lpad - Ltot)    // 60
__global__ void fill_memkv_kernel(const float* __restrict__ mem) {
    int blk = blockIdx.x;
    int bh = blk >> 3, part = blk & 7;
    int h = bh & 7, b = bh >> 3;
    int t = threadIdx.x;
    const bf16 z = __float2bfloat16(0.f);

    if (part == 0) {
        int l = t >> 6, d = t & 63;
        float kv = mem[((size_t)h*DH + d)*NKV + l];
        float vv = mem[((size_t)(NH + h)*DH + d)*NKV + l];
        bf16 kh = __float2bfloat16(kv);
        bf16 vh = __float2bfloat16(vv);
        size_t ki = ((size_t)bh*Lpad + l)*DH + d;
        size_t vi = ((size_t)bh*DH + d)*Lpad + l;
        d_khi[ki] = kh; d_klo[ki] = __float2bfloat16(kv - __bfloat162float(kh));
        d_vhi[vi] = vh; d_vlo[vi] = __float2bfloat16(vv - __bfloat162float(vh));
    }
    if (part < 4) {
        int seg = part;
        for (int i = t; i < 15*DH; i += 256) {
            int r = seg*15 + i / DH, d = i % DH;
            size_t ki = ((size_t)bh*Lpad + Ltot + r)*DH + d;
            d_khi[ki] = z; d_klo[ki] = z;
        }
    } else {
        int seg = part & 3;
        for (int i = t; i < 16*PADT; i += 256) {
            int d = seg*16 + i / PADT, off = i % PADT;
            size_t vi = ((size_t)bh*DH + d)*Lpad + Ltot + off;
            d_vhi[vi] = z; d_vlo[vi] = z;
        }
    }
}

// ------------------------- bf16x3 mma.sync mainloop (single-buffered; occupancy hides loads) ----
#define SA_HI 0u
#define SA_LO 16384u
#define SB_HI 32768u
#define SB_LO 49152u
#define GEMM_SMEM_BYTES 65536

__device__ __forceinline__ void gemm_bf16x3_acc(
    const bf16* __restrict__ Ahi, const bf16* __restrict__ Alo,
    const bf16* __restrict__ Bhi, const bf16* __restrict__ Blo,
    char* smem, float acc[4][4][4])
{
    const int tid = threadIdx.x;
    const int w = tid >> 5, l = tid & 31;
    const int mb = (w >> 2) * 64, nb = (w & 3) * 32;
    const uint32_t sbase = smem_u32_of(smem);

    const int arow = (l & 7) + ((l >> 3) & 1) * 8;
    const int acol = (l & 16) ? 16 : 0;
    const int brow = l & 7;
    const int bcol = (l & 8) ? 16 : 0;

    const bf16* srcs[4] = {Ahi, Alo, Bhi, Blo};

    for (int ch = 0; ch < 8; ch++) {
        if (ch) __syncthreads();
        int k0 = ch * 64;
#pragma unroll
        for (int tI = 0; tI < 4; tI++) {
            const char* src = (const char*)srcs[tI] + k0*2;
            uint32_t tb = tI * 16384u;
#pragma unroll
            for (int it = 0; it < 4; it++) {
                int idx = tid + it*256;
                int row = idx >> 3, u = idx & 7;
                uint4 v = *(const uint4*)(src + (size_t)row*1024 + u*16);
                uint32_t boff = (uint32_t)row*128u + (uint32_t)u*16u;
                *(uint4*)(smem + tb + SW128B(boff)) = v;
            }
        }
        __syncthreads();

#pragma unroll
        for (int ks = 0; ks < 4; ks++) {
            int kb = ks * 32;
            uint32_t ah[4][4], al[4][4];
#pragma unroll
            for (int mt = 0; mt < 4; mt++) {
                uint32_t off = SW128B((uint32_t)(mb + mt*16 + arow)*128u + kb + acol);
                ldm_x4(ah[mt], sbase + SA_HI + off);
                ldm_x4(al[mt], sbase + SA_LO + off);
            }
            uint32_t bh[4][2], bl[4][2];
#pragma unroll
            for (int nt = 0; nt < 4; nt++) {
                uint32_t off = SW128B((uint32_t)(nb + nt*8 + brow)*128u + kb + bcol);
                ldm_x2(bh[nt], sbase + SB_HI + off);
                ldm_x2(bl[nt], sbase + SB_LO + off);
            }
#pragma unroll
            for (int mt = 0; mt < 4; mt++)
#pragma unroll
                for (int nt = 0; nt < 4; nt++) {
                    mma_bf16(acc[mt][nt], ah[mt], bh[nt]);
                    mma_bf16(acc[mt][nt], al[mt], bh[nt]);
                    mma_bf16(acc[mt][nt], ah[mt], bl[nt]);
                }
        }
    }
}

// ------------------------- QKV GEMM (mma.sync bf16x3) -> bf16 hi/lo q/k/v -------------------------
__global__ __launch_bounds__(256, 1) void qkv_mma_kernel() {
    extern __shared__ __align__(16) char smem[];
    int b = blockIdx.z, m0 = blockIdx.x * 128, n0 = blockIdx.y * 128;

    float acc[4][4][4];
#pragma unroll
    for (int i = 0; i < 4; i++)
#pragma unroll
        for (int j = 0; j < 4; j++)
#pragma unroll
            for (int r = 0; r < 4; r++) acc[i][j][r] = 0.f;

    gemm_bf16x3_acc(d_thi + ((size_t)b*Nn + m0)*Cc, d_tlo + ((size_t)b*Nn + m0)*Cc,
                    d_whi + (size_t)n0*Cc,          d_wlo + (size_t)n0*Cc,
                    smem, acc);

    const int tid = threadIdx.x, w = tid >> 5, l = tid & 31;
    const int mb = (w >> 2) * 64, nb = (w & 3) * 32;
    const int trow = l >> 2, tcol = (l & 3) * 2;
    const int sec = n0 >> 9;     // 0=q 1=k 2=v
    const float mult = (sec == 0) ? SCALE : 1.f;

#pragma unroll
    for (int mt = 0; mt < 4; mt++) {
#pragma unroll
        for (int nt = 0; nt < 4; nt++) {
            int tok = m0 + mb + mt*16 + trow;
            int j   = n0 + nb + nt*8 + tcol;
            int jl  = j & 511;
            int hh  = jl >> 6, dd = jl & 63;
            int bh  = b*NH + hh;
            float* a4 = acc[mt][nt];
            if (sec == 2) {
#pragma unroll
                for (int e = 0; e < 4; e++) {
                    float v = a4[e];
                    int ddx = dd + (e & 1);
                    int tk  = NKV + tok + (e >> 1)*8;
                    bf16 h = __float2bfloat16(v);
                    size_t idx = ((size_t)bh*DH + ddx)*Lpad + tk;
                    d_vhi[idx] = h;
                    d_vlo[idx] = __float2bfloat16(v - __bfloat162float(h));
                }
            } else {
                bf16* ahp; bf16* alp; size_t ridx0, ridx1;
                if (sec == 0) {
                    ahp = d_qhi; alp = d_qlo;
                    ridx0 = ((size_t)bh*Nn + tok)*DH + dd;
                    ridx1 = ((size_t)bh*Nn + tok + 8)*DH + dd;
                } else {
                    ahp = d_khi; alp = d_klo;
                    ridx0 = ((size_t)bh*Lpad + NKV + tok)*DH + dd;
                    ridx1 = ((size_t)bh*Lpad + NKV + tok + 8)*DH + dd;
                }
                uint32_t h32, l32;
                split2(a4[0]*mult, a4[1]*mult, h32, l32);
                *(uint32_t*)(ahp + ridx0) = h32;
                *(uint32_t*)(alp + ridx0) = l32;
                split2(a4[2]*mult, a4[3]*mult, h32, l32);
                *(uint32_t*)(ahp + ridx1) = h32;
                *(uint32_t*)(alp + ridx1) = l32;
            }
        }
    }
}

// ------------------------- output projection GEMM + GN2 group partials -------------------------
__global__ __launch_bounds__(256, 1) void out_mma_kernel(const float* __restrict__ bout) {
    extern __shared__ __align__(16) char smem[];
    int b = blockIdx.z, m0 = blockIdx.x * 128, n0 = blockIdx.y * 128;

    float acc[4][4][4];
#pragma unroll
    for (int i = 0; i < 4; i++)
#pragma unroll
        for (int j = 0; j < 4; j++)
#pragma unroll
            for (int r = 0; r < 4; r++) acc[i][j][r] = 0.f;

    gemm_bf16x3_acc(d_ohi + ((size_t)b*Nn + m0)*HID, d_olo + ((size_t)b*Nn + m0)*HID,
                    d_wohi + (size_t)n0*HID,         d_wolo + (size_t)n0*HID,
                    smem, acc);

    const int tid = threadIdx.x, w = tid >> 5, l = tid & 31;
    const int mb = (w >> 2) * 64, nb = (w & 3) * 32;
    const int trow = l >> 2, tcol = (l & 3) * 2;

    float gsum[2] = {0.f, 0.f}, gsq[2] = {0.f, 0.f};

#pragma unroll
    for (int mt = 0; mt < 4; mt++) {
#pragma unroll
        for (int nt = 0; nt < 4; nt++) {
            int tok = m0 + mb + mt*16 + trow;
            int cc  = n0 + nb + nt*8 + tcol;
            float b0 = bout[cc], b1 = bout[cc+1];
            float* a4 = acc[mt][nt];
            float v0 = a4[0] + b0, v1 = a4[1] + b1;
            float v2 = a4[2] + b0, v3 = a4[3] + b1;
            d_y[((size_t)b*Cc + cc)*Nn + tok]       = v0;
            d_y[((size_t)b*Cc + cc+1)*Nn + tok]     = v1;
            d_y[((size_t)b*Cc + cc)*Nn + tok + 8]   = v2;
            d_y[((size_t)b*Cc + cc+1)*Nn + tok + 8] = v3;
            const int e = nt >> 1;
            gsum[e] += v0 + v1 + v2 + v3;
            gsq[e]  += v0*v0 + v1*v1 + v2*v2 + v3*v3;
        }
    }

#pragma unroll
    for (int off = 16; off; off >>= 1) {
        gsum[0] += __shfl_xor_sync(~0u, gsum[0], off);
        gsum[1] += __shfl_xor_sync(~0u, gsum[1], off);
        gsq[0]  += __shfl_xor_sync(~0u, gsq[0],  off);
        gsq[1]  += __shfl_xor_sync(~0u, gsq[1],  off);
    }
    __shared__ float sm_w[8][2][2];
    if (l == 0) {
        sm_w[w][0][0] = gsum[0]; sm_w[w][0][1] = gsq[0];
        sm_w[w][1][0] = gsum[1]; sm_w[w][1][1] = gsq[1];
    }
    __syncthreads();
    if (tid < 16) {
        int gg = tid >> 1, j = tid & 1;
        int p = gg >> 1, e = gg & 1;
        float v = sm_w[p][e][j] + sm_w[4 + p][e][j];
        int cta = (b*OUT_NY + blockIdx.y)*OUT_NX + blockIdx.x;
        d_part[(cta*8 + gg)*2 + j] = v;
    }
}

// ------------------------- GN2 finalize: partials -> per-channel affine -------------------------
__global__ void gn2_finalize_kernel(const float* __restrict__ w,
                                    const float* __restrict__ bgn) {
    int t = threadIdx.x;            // 64 = Bb*Gg
    int b = t >> 5, g = t & 31;
    int ny = g >> 3, gg = g & 7;
    float s = 0.f, q = 0.f;
    for (int nx = 0; nx < OUT_NX; nx++) {
        int cta = (b*OUT_NY + ny)*OUT_NX + nx;
        s += d_part[(cta*8 + gg)*2 + 0];
        q += d_part[(cta*8 + gg)*2 + 1];
    }
    float inv = 1.f / (float)(CG*Nn);
    float mu = s * inv;
    float var = q * inv - mu*mu;
    float rs = rsqrtf(var + 1e-5f);
#pragma unroll
    for (int i = 0; i < CG; i++) {
        int c = g*CG + i;
        float sc = rs * w[c];
        d_s2[b*Cc + c] = sc;
        d_b2[b*Cc + c] = bgn[c] - mu*sc;
    }
}

// ------------------------- Flash attention: KT=64, 96KB smem, 2 CTAs/SM, sub-chunked softmax ----
// smem: buf A @0 (32K): [KH 8K | KL 8K | VH 8K | VL 8K]
//       buf B @32K: same layout; initially Q [QH 16K | QL 16K] (reused after frag load)
//       P @64K: [PH 16K | PL 16K].  total 96K.
#define FK_H 0u
#define FK_L 8192u
#define FV_H 16384u
#define FV_L 24576u
#define F_BUF(b) ((uint32_t)(b)*32768u)
#define F2_QH 32768u
#define F2_QL 49152u
#define F2_PH 65536u
#define F2_PL 81920u
#define FLASH_SMEM_BYTES 98304

__device__ __forceinline__ void flash_prefetch(uint32_t sb, int bh, int kt, uint32_t bufb, int tid) {
    const bf16* kh_g = d_khi + ((size_t)bh*Lpad + kt*KT2)*DH;
    const bf16* kl_g = d_klo + ((size_t)bh*Lpad + kt*KT2)*DH;
#pragma unroll
    for (int i = 0; i < 2; i++) {
        int idx = tid + i*256;
        int row = idx >> 3, u = idx & 7;
        uint32_t so = SW128B((uint32_t)row*128u + (uint32_t)u*16u);
        cpa16(sb + bufb + FK_H + so, kh_g + (size_t)row*DH + u*8);
        cpa16(sb + bufb + FK_L + so, kl_g + (size_t)row*DH + u*8);
    }
    const bf16* vh_g = d_vhi + (size_t)bh*DH*Lpad + kt*KT2;
    const bf16* vl_g = d_vlo + (size_t)bh*DH*Lpad + kt*KT2;
#pragma unroll
    for (int i = 0; i < 2; i++) {
        int idx = tid + i*256;
        int dd = idx >> 3, u = idx & 7;
        uint32_t so = SW128B((uint32_t)dd*128u + (uint32_t)u*16u);
        cpa16(sb + bufb + FV_H + so, vh_g + (size_t)dd*Lpad + u*8);
        cpa16(sb + bufb + FV_L + so, vl_g + (size_t)dd*Lpad + u*8);
    }
}

__global__ __launch_bounds__(256, 2) void flash_mma_kernel() {
    extern __shared__ __align__(16) char smem[];
    const uint32_t sb = smem_u32_of(smem);
    const int qt = blockIdx.x, h = blockIdx.y, b = blockIdx.z;
    const int bh = b*NH + h;
    const int tid = threadIdx.x, w = tid >> 5, l = tid & 31;
    const int trow = l >> 2, tcol = (l & 3) * 2;

    // ---- prologue: Q (into buf B region) + tile0 (buf A) via cp.async ----
    const bf16* qh_g = d_qhi + ((size_t)bh*Nn + qt*128)*DH;
    const bf16* ql_g = d_qlo + ((size_t)bh*Nn + qt*128)*DH;
#pragma unroll
    for (int i = 0; i < 4; i++) {
        int idx = tid + i*256;
        int row = idx >> 3, u = idx & 7;
        uint32_t so = SW128B((uint32_t)row*128u + (uint32_t)u*16u);
        cpa16(sb + F2_QH + so, qh_g + (size_t)row*DH + u*8);
        cpa16(sb + F2_QL + so, ql_g + (size_t)row*DH + u*8);
    }
    flash_prefetch(sb, bh, 0, F_BUF(0), tid);
    CP_COMMIT();
    CP_WAIT0();
    __syncthreads();

    const int arow = (l & 7) + ((l >> 3) & 1) * 8;
    const int acol = (l & 16) ? 16 : 0;
    const int xrow = ((l >> 4) & 1) * 8 + (l & 7);
    const int xcol = ((l >> 3) & 1) * 16;
    uint32_t qfh[4][4], qfl[4][4];
#pragma unroll
    for (int ks = 0; ks < 4; ks++) {
        uint32_t off = SW128B((uint32_t)(w*16 + arow)*128u + ks*32 + acol);
        ldm_x4(qfh[ks], sb + F2_QH + off);
        ldm_x4(qfl[ks], sb + F2_QL + off);
    }
    __syncthreads();   // Q region free for reuse as buf B

    float mrow[2] = {-1e30f, -1e30f};
    float lrow[2] = {0.f, 0.f};
    float oacc[8][4];
#pragma unroll
    for (int nt = 0; nt < 8; nt++)
#pragma unroll
        for (int r = 0; r < 4; r++) oacc[nt][r] = 0.f;

    for (int kt = 0; kt < NKT2; kt++) {
        const uint32_t bufb = F_BUF(kt & 1);
        const bool tail = (kt == NKT2 - 1);
        if (kt + 1 < NKT2) {
            flash_prefetch(sb, bh, kt + 1, F_BUF((kt + 1) & 1), tid);
            CP_COMMIT();
        }

        // ---- two 32-key subchunks: QK -> softmax -> P -> PV  (sacc is 16 regs) ----
#pragma unroll
        for (int sc = 0; sc < 2; sc++) {
            if (sc == 1 && tail) continue;   // tail subchunk 1 fully masked

            float sacc[4][4];
#pragma unroll
            for (int nt = 0; nt < 4; nt++)
#pragma unroll
                for (int r = 0; r < 4; r++) sacc[nt][r] = 0.f;

            // QK for this subchunk (n-pairs 2sc, 2sc+1; tail computes pair 0 only)
#pragma unroll
            for (int ks = 0; ks < 4; ks++) {
#pragma unroll
                for (int nl = 0; nl < 2; nl++) {
                    if (nl == 0 || !tail) {
                        const int nt2 = 2*sc + nl;
                        uint32_t off = SW128B((uint32_t)(nt2*16 + xrow)*128u + ks*32 + xcol);
                        uint32_t kh4[4], kl4[4];
                        ldm_x4(kh4, sb + bufb + FK_H + off);
                        ldm_x4(kl4, sb + bufb + FK_L + off);
                        mma_bf16(sacc[2*nl],   qfh[ks], kh4);
                        mma_bf16(sacc[2*nl],   qfl[ks], kh4);
                        mma_bf16(sacc[2*nl],   qfh[ks], kl4);
                        mma_bf16(sacc[2*nl+1], qfh[ks], kh4+2);
                        mma_bf16(sacc[2*nl+1], qfl[ks], kh4+2);
                        mma_bf16(sacc[2*nl+1], qfh[ks], kl4+2);
                    }
                }
            }

            // mask (tail, sc==0): keys (NKT2-1)*64 + nt*8 + tcol
            if (tail) {
#pragma unroll
                for (int nt = 0; nt < 4; nt++) {
                    int k0i = (NKT2-1)*KT2 + nt*8 + tcol;
                    if (k0i >= Ltot)     { sacc[nt][0] = -1e30f; sacc[nt][2] = -1e30f; }
                    if (k0i + 1 >= Ltot) { sacc[nt][1] = -1e30f; sacc[nt][3] = -1e30f; }
                }
            }

            // online softmax over this 32-key subchunk
#pragma unroll
            for (int r = 0; r < 2; r++) {
                int ro = 2*r;
                float rm = -1e30f;
#pragma unroll
                for (int nt = 0; nt < 4; nt++)
                    rm = fmaxf(rm, fmaxf(sacc[nt][ro], sacc[nt][ro+1]));
                rm = fmaxf(rm, __shfl_xor_sync(~0u, rm, 1, 4));
                rm = fmaxf(rm, __shfl_xor_sync(~0u, rm, 2, 4));
                float mn = fmaxf(mrow[r], rm);
                float alpha = __expf(mrow[r] - mn);
                mrow[r] = mn;
                float rs = 0.f;
#pragma unroll
                for (int nt = 0; nt < 4; nt++) {
                    float p0 = __expf(sacc[nt][ro]   - mn);
                    float p1 = __expf(sacc[nt][ro+1] - mn);
                    sacc[nt][ro] = p0; sacc[nt][ro+1] = p1;
                    rs += p0 + p1;
                }
                rs += __shfl_xor_sync(~0u, rs, 1, 4);
                rs += __shfl_xor_sync(~0u, rs, 2, 4);
                lrow[r] = lrow[r]*alpha + rs;
#pragma unroll
                for (int nt = 0; nt < 8; nt++) {
                    oacc[nt][ro] *= alpha; oacc[nt][ro+1] *= alpha;
                }
            }

            // write P hi/lo (cols sc*32 .. sc*32+31; warp-private rows)
#pragma unroll
            for (int nt = 0; nt < 4; nt++) {
                int col = sc*32 + nt*8 + tcol;
                uint32_t bc = (uint32_t)col * 2u;
                uint32_t h32, l32;
                split2(sacc[nt][0], sacc[nt][1], h32, l32);
                uint32_t o0 = SW128B((uint32_t)(w*16 + trow)*128u + bc);
                *(uint32_t*)(smem + F2_PH + o0) = h32;
                *(uint32_t*)(smem + F2_PL + o0) = l32;
                split2(sacc[nt][2], sacc[nt][3], h32, l32);
                uint32_t o1 = SW128B((uint32_t)(w*16 + trow + 8)*128u + bc);
                *(uint32_t*)(smem + F2_PH + o1) = h32;
                *(uint32_t*)(smem + F2_PL + o1) = l32;
            }
            __syncwarp();

            // O += P V over this subchunk (k-steps 2sc, 2sc+1; tail only first)
#pragma unroll
            for (int kl2 = 0; kl2 < 2; kl2++) {
                if (kl2 == 0 || !tail) {
                    const int ks2 = 2*sc + kl2;
                    uint32_t kb = (uint32_t)ks2 * 32u;
                    uint32_t pfh[4], pfl[4];
                    uint32_t offA = SW128B((uint32_t)(w*16 + arow)*128u + kb + acol);
                    ldm_x4(pfh, sb + F2_PH + offA);
                    ldm_x4(pfl, sb + F2_PL + offA);
#pragma unroll
                    for (int nt2 = 0; nt2 < 4; nt2++) {
                        uint32_t offB = SW128B((uint32_t)(nt2*16 + xrow)*128u + kb + xcol);
                        uint32_t vh4[4], vl4[4];
                        ldm_x4(vh4, sb + bufb + FV_H + offB);
                        ldm_x4(vl4, sb + bufb + FV_L + offB);
                        mma_bf16(oacc[2*nt2],   pfh, vh4);
                        mma_bf16(oacc[2*nt2],   pfl, vh4);
                        mma_bf16(oacc[2*nt2],   pfh, vl4);
                        mma_bf16(oacc[2*nt2+1], pfh, vh4+2);
                        mma_bf16(oacc[2*nt2+1], pfl, vh4+2);
                        mma_bf16(oacc[2*nt2+1], pfh, vl4+2);
                    }
                }
            }
        }

        if (kt + 1 < NKT2) {
            CP_WAIT0();
            __syncthreads();
        }
    }

    // ---- epilogue ----
#pragma unroll
    for (int r = 0; r < 2; r++) {
        float inv = 1.f / lrow[r];
        int tok = qt*128 + w*16 + trow + r*8;
        size_t rowb = (size_t)(b*Nn + tok)*HID + h*DH;
#pragma unroll
        for (int nt = 0; nt < 8; nt++) {
            uint32_t h32, l32;
            split2(oacc[nt][2*r]*inv, oacc[nt][2*r+1]*inv, h32, l32);
            int col = nt*8 + tcol;
            *(uint32_t*)(d_ohi + rowb + col) = h32;
            *(uint32_t*)(d_olo + rowb + col) = l32;
        }
    }
}

// ------------------------- GN2 apply -> final output -------------------------
__global__ void gn_apply_kernel(float* __restrict__ out) {
    int f = blockIdx.x * 256 + threadIdx.x;
    float4 v = ((const float4*)d_y)[f];
    int bc = f / (Nn/4);
    float s = d_s2[bc], bb = d_b2[bc];
    float4 r;
    r.x = v.x*s + bb; r.y = v.y*s + bb; r.z = v.z*s + bb; r.w = v.w*s + bb;
    ((float4*)out)[f] = r;
}

// ------------------------- launch -------------------------
extern "C" void kernel_launch(void* const* d_in, const int* in_sizes, int n_in,
                              void* d_out, int out_size) {
    const float* x     = (const float*)d_in[0];
    const float* gn1_w = (const float*)d_in[1];
    const float* gn1_b = (const float*)d_in[2];
    const float* w_qkv = (const float*)d_in[3];
    const float* memkv = (const float*)d_in[4];
    const float* w_out = (const float*)d_in[5];
    const float* b_out = (const float*)d_in[6];
    const float* gn2_w = (const float*)d_in[7];
    const float* gn2_b = (const float*)d_in[8];
    float* out = (float*)d_out;

    static bool attr_set = false;
    if (!attr_set) {
        cudaFuncSetAttribute(flash_mma_kernel, cudaFuncAttributeMaxDynamicSharedMemorySize, FLASH_SMEM_BYTES);
        cudaFuncSetAttribute(qkv_mma_kernel,   cudaFuncAttributeMaxDynamicSharedMemorySize, GEMM_SMEM_BYTES);
        cudaFuncSetAttribute(out_mma_kernel,   cudaFuncAttributeMaxDynamicSharedMemorySize, GEMM_SMEM_BYTES);
        attr_set = true;
    }

    float *p_s1, *p_b1;
    cudaGetSymbolAddress((void**)&p_s1, d_s1);
    cudaGetSymbolAddress((void**)&p_b1, d_b1);

    gn_stats_kernel<<<Bb*Gg, 256>>>(x, gn1_w, gn1_b, p_s1, p_b1);
    prep_x_kernel<<<dim3(Nn/32, Cc/32, Bb), 256>>>(x);
    split_both_kernel<<<SPLIT1_BLOCKS + (Cc*HID)/256, 256>>>(w_qkv, w_out);
    fill_memkv_kernel<<<Bb*NH*8, 256>>>(memkv);
    qkv_mma_kernel<<<dim3(Nn/128, QKVJ/128, Bb), 256, GEMM_SMEM_BYTES>>>();
    flash_mma_kernel<<<dim3(Nn/128, NH, Bb), 256, FLASH_SMEM_BYTES>>>();
    out_mma_kernel<<<dim3(OUT_NX, OUT_NY, Bb), 256, GEMM_SMEM_BYTES>>>(b_out);
    gn2_finalize_kernel<<<1, 64>>>(gn2_w, gn2_b);
    gn_apply_kernel<<<(Bb*Cc*Nn/4)/256, 256>>>(out);
}

// round 16
// speedup vs baseline: 1.0128x; 1.0128x over previous
#include <cuda_runtime.h>
#include <cuda_bf16.h>
#include <cstdint>

#define Bb   2
#define Cc   512
#define Nn   2304          // 48*48
#define Gg   32
#define CG   16            // Cc/Gg
#define NH   8
#define DH   64
#define HID  512
#define QKVJ 1536
#define NKV  4
#define Ltot 2308          // Nn + NKV
#define Lpad 2368          // 37*64
#define KT2  64
#define NKT2 37
#define SCALE 0.125f       // DH^-0.5
#define OUT_NX 18          // Nn/128
#define OUT_NY 4           // HID/128

typedef unsigned long long u64;
typedef __nv_bfloat16 bf16;

// byte swizzle for 128-byte rows (mma smem tiles)
#define SW128B(o) ((o) ^ (((o) >> 3) & 0x70))

// ---------- mma.sync helpers ----------
__device__ __forceinline__ uint32_t smem_u32_of(const void* p) {
    uint32_t a;
    asm("{ .reg .u64 t; cvta.to.shared.u64 t, %1; cvt.u32.u64 %0, t; }" : "=r"(a) : "l"(p));
    return a;
}
__device__ __forceinline__ void ldm_x4(uint32_t r[4], uint32_t a) {
    asm volatile("ldmatrix.sync.aligned.m8n8.x4.shared.b16 {%0,%1,%2,%3}, [%4];"
        : "=r"(r[0]), "=r"(r[1]), "=r"(r[2]), "=r"(r[3]) : "r"(a));
}
__device__ __forceinline__ void ldm_x2(uint32_t r[2], uint32_t a) {
    asm volatile("ldmatrix.sync.aligned.m8n8.x2.shared.b16 {%0,%1}, [%2];"
        : "=r"(r[0]), "=r"(r[1]) : "r"(a));
}
__device__ __forceinline__ void mma_bf16(float d[4], const uint32_t a[4], const uint32_t b[2]) {
    asm volatile(
        "mma.sync.aligned.m16n8k16.row.col.f32.bf16.bf16.f32 "
        "{%0,%1,%2,%3}, {%4,%5,%6,%7}, {%8,%9}, {%0,%1,%2,%3};"
        : "+f"(d[0]), "+f"(d[1]), "+f"(d[2]), "+f"(d[3])
        : "r"(a[0]), "r"(a[1]), "r"(a[2]), "r"(a[3]), "r"(b[0]), "r"(b[1]));
}
__device__ __forceinline__ void cpa16(uint32_t s, const void* g) {
    asm volatile("cp.async.cg.shared.global [%0], [%1], 16;" :: "r"(s), "l"(g));
}
#define CP_COMMIT() asm volatile("cp.async.commit_group;" ::: "memory")
#define CP_WAIT0()  asm volatile("cp.async.wait_group 0;" ::: "memory")

// pack two floats to bf16x2 hi + residual lo
__device__ __forceinline__ void split2(float a, float b, uint32_t& hi, uint32_t& lo) {
    __nv_bfloat162 h, l2;
    h.x = __float2bfloat16(a); h.y = __float2bfloat16(b);
    l2.x = __float2bfloat16(a - __bfloat162float(h.x));
    l2.y = __float2bfloat16(b - __bfloat162float(h.y));
    hi = *(uint32_t*)&h; lo = *(uint32_t*)&l2;
}

// ------------------------- scratch (device globals) -------------------------
__device__ float d_s1[Bb*Cc], d_b1[Bb*Cc], d_s2[Bb*Cc], d_b2[Bb*Cc];
__device__ bf16 d_thi[(size_t)Bb*Nn*Cc],  d_tlo[(size_t)Bb*Nn*Cc];   // tokens [b][tok][c]
__device__ bf16 d_whi[(size_t)QKVJ*Cc],   d_wlo[(size_t)QKVJ*Cc];    // w_qkv  [j][c]
__device__ bf16 d_wohi[(size_t)Cc*HID],   d_wolo[(size_t)Cc*HID];    // w_out  [c][j]
__device__ bf16 d_qhi[(size_t)Bb*NH*Nn*DH],   d_qlo[(size_t)Bb*NH*Nn*DH];    // [b,h][tok][d] prescaled
__device__ bf16 d_khi[(size_t)Bb*NH*Lpad*DH], d_klo[(size_t)Bb*NH*Lpad*DH];  // [b,h][tok][d]
__device__ bf16 d_vhi[(size_t)Bb*NH*DH*Lpad], d_vlo[(size_t)Bb*NH*DH*Lpad];  // [b,h][d][tok]
__device__ bf16 d_ohi[(size_t)Bb*Nn*HID], d_olo[(size_t)Bb*Nn*HID];  // attn out [b][tok][j]
__device__ float d_y[(size_t)Bb*Cc*Nn];
__device__ float d_part[Bb*OUT_NY*OUT_NX*8*2];   // GN2 per-CTA group partials (sum, sumsq)

// ------------------------- GroupNorm stats -> affine (input GN) -------------------------
__global__ void gn_stats_kernel(const float* __restrict__ src,
                                const float* __restrict__ w,
                                const float* __restrict__ bgn,
                                float* __restrict__ sout,
                                float* __restrict__ bout) {
    int b = blockIdx.x >> 5;
    int g = blockIdx.x & 31;
    const float* p = src + ((size_t)b*Cc + g*CG) * Nn;
    float sum = 0.f, sq = 0.f;
    for (int i = threadIdx.x; i < CG*Nn; i += 256) {
        float v = p[i]; sum += v; sq += v*v;
    }
    __shared__ float r0[8], r1[8];
    __shared__ float smu, srs;
    int lane = threadIdx.x & 31, wid = threadIdx.x >> 5;
#pragma unroll
    for (int off = 16; off; off >>= 1) {
        sum += __shfl_xor_sync(~0u, sum, off);
        sq  += __shfl_xor_sync(~0u, sq,  off);
    }
    if (!lane) { r0[wid] = sum; r1[wid] = sq; }
    __syncthreads();
    if (threadIdx.x == 0) {
        float s = 0.f, q = 0.f;
#pragma unroll
        for (int i = 0; i < 8; i++) { s += r0[i]; q += r1[i]; }
        float inv = 1.f / (float)(CG*Nn);
        float mu  = s * inv;
        float var = q * inv - mu*mu;
        smu = mu; srs = rsqrtf(var + 1e-5f);
    }
    __syncthreads();
    if (threadIdx.x < CG) {
        int c = g*CG + threadIdx.x;
        float ww = w[c];
        float sc = srs * ww;
        sout[b*Cc + c] = sc;
        bout[b*Cc + c] = bgn[c] - smu * sc;
    }
}

// ------------------------- prep: transpose x + GN1 affine + bf16 split -------------------------
__global__ void prep_x_kernel(const float* __restrict__ x) {
    __shared__ float t[32][33];
    int b = blockIdx.z;
    int c0 = blockIdx.y * 32;
    int t0 = blockIdx.x * 32;
    int lx = threadIdx.x & 31, ly = threadIdx.x >> 5;
#pragma unroll
    for (int i = 0; i < 4; i++) {
        int c = c0 + ly + i*8;
        float v = x[((size_t)b*Cc + c)*Nn + t0 + lx];
        t[ly + i*8][lx] = v * d_s1[b*Cc + c] + d_b1[b*Cc + c];
    }
    __syncthreads();
#pragma unroll
    for (int i = 0; i < 4; i++) {
        int tok = t0 + ly + i*8;
        int c = c0 + lx;
        float v = t[lx][ly + i*8];
        bf16 hi = __float2bfloat16(v);
        bf16 lo = __float2bfloat16(v - __bfloat162float(hi));
        size_t idx = ((size_t)b*Nn + tok)*Cc + c;
        d_thi[idx] = hi; d_tlo[idx] = lo;
    }
}

// ------------------------- prep: weight splits + memkv prepend, one launch -------------------------
#define SPLIT1_BLOCKS ((QKVJ*Cc)/256)
#define SPLIT2_BLOCKS ((Cc*HID)/256)
#define SPLIT_TOTAL   (SPLIT1_BLOCKS + SPLIT2_BLOCKS)
#define PADT (Lpad - Ltot)    // 60
__global__ void prep_misc_kernel(const float* __restrict__ w_qkv,
                                 const float* __restrict__ w_out,
                                 const float* __restrict__ mem) {
    int blk = blockIdx.x;
    int t = threadIdx.x;
    if (blk < SPLIT_TOTAL) {
        const float* src; bf16 *hi, *lo; int i;
        if (blk < SPLIT1_BLOCKS) {
            src = w_qkv; hi = d_whi; lo = d_wlo;
            i = blk * 256 + t;
        } else {
            src = w_out; hi = d_wohi; lo = d_wolo;
            i = (blk - SPLIT1_BLOCKS) * 256 + t;
        }
        float v = src[i];
        bf16 h = __float2bfloat16(v);
        hi[i] = h;
        lo[i] = __float2bfloat16(v - __bfloat162float(h));
        return;
    }
    // memkv part
    int mblk = blk - SPLIT_TOTAL;
    int bh = mblk >> 3, part = mblk & 7;
    int h = bh & 7, b = bh >> 3;
    const bf16 z = __float2bfloat16(0.f);

    if (part == 0) {
        int l = t >> 6, d = t & 63;
        float kv = mem[((size_t)h*DH + d)*NKV + l];
        float vv = mem[((size_t)(NH + h)*DH + d)*NKV + l];
        bf16 kh = __float2bfloat16(kv);
        bf16 vh = __float2bfloat16(vv);
        size_t ki = ((size_t)bh*Lpad + l)*DH + d;
        size_t vi = ((size_t)bh*DH + d)*Lpad + l;
        d_khi[ki] = kh; d_klo[ki] = __float2bfloat16(kv - __bfloat162float(kh));
        d_vhi[vi] = vh; d_vlo[vi] = __float2bfloat16(vv - __bfloat162float(vh));
    }
    if (part < 4) {
        int seg = part;
        for (int i = t; i < 15*DH; i += 256) {
            int r = seg*15 + i / DH, d = i % DH;
            size_t ki = ((size_t)bh*Lpad + Ltot + r)*DH + d;
            d_khi[ki] = z; d_klo[ki] = z;
        }
    } else {
        int seg = part & 3;
        for (int i = t; i < 16*PADT; i += 256) {
            int d = seg*16 + i / PADT, off = i % PADT;
            size_t vi = ((size_t)bh*DH + d)*Lpad + Ltot + off;
            d_vhi[vi] = z; d_vlo[vi] = z;
        }
    }
}

// ------------------------- bf16x3 mma.sync mainloop (single-buffered) -------------------------
#define SA_HI 0u
#define SA_LO 16384u
#define SB_HI 32768u
#define SB_LO 49152u
#define GEMM_SMEM_BYTES 65536

__device__ __forceinline__ void gemm_bf16x3_acc(
    const bf16* __restrict__ Ahi, const bf16* __restrict__ Alo,
    const bf16* __restrict__ Bhi, const bf16* __restrict__ Blo,
    char* smem, float acc[4][4][4])
{
    const int tid = threadIdx.x;
    const int w = tid >> 5, l = tid & 31;
    const int mb = (w >> 2) * 64, nb = (w & 3) * 32;
    const uint32_t sbase = smem_u32_of(smem);

    const int arow = (l & 7) + ((l >> 3) & 1) * 8;
    const int acol = (l & 16) ? 16 : 0;
    const int brow = l & 7;
    const int bcol = (l & 8) ? 16 : 0;

    const bf16* srcs[4] = {Ahi, Alo, Bhi, Blo};

    for (int ch = 0; ch < 8; ch++) {
        if (ch) __syncthreads();
        int k0 = ch * 64;
#pragma unroll
        for (int tI = 0; tI < 4; tI++) {
            const char* src = (const char*)srcs[tI] + k0*2;
            uint32_t tb = tI * 16384u;
#pragma unroll
            for (int it = 0; it < 4; it++) {
                int idx = tid + it*256;
                int row = idx >> 3, u = idx & 7;
                uint4 v = *(const uint4*)(src + (size_t)row*1024 + u*16);
                uint32_t boff = (uint32_t)row*128u + (uint32_t)u*16u;
                *(uint4*)(smem + tb + SW128B(boff)) = v;
            }
        }
        __syncthreads();

#pragma unroll
        for (int ks = 0; ks < 4; ks++) {
            int kb = ks * 32;
            uint32_t ah[4][4], al[4][4];
#pragma unroll
            for (int mt = 0; mt < 4; mt++) {
                uint32_t off = SW128B((uint32_t)(mb + mt*16 + arow)*128u + kb + acol);
                ldm_x4(ah[mt], sbase + SA_HI + off);
                ldm_x4(al[mt], sbase + SA_LO + off);
            }
            uint32_t bh[4][2], bl[4][2];
#pragma unroll
            for (int nt = 0; nt < 4; nt++) {
                uint32_t off = SW128B((uint32_t)(nb + nt*8 + brow)*128u + kb + bcol);
                ldm_x2(bh[nt], sbase + SB_HI + off);
                ldm_x2(bl[nt], sbase + SB_LO + off);
            }
#pragma unroll
            for (int mt = 0; mt < 4; mt++)
#pragma unroll
                for (int nt = 0; nt < 4; nt++) {
                    mma_bf16(acc[mt][nt], ah[mt], bh[nt]);
                    mma_bf16(acc[mt][nt], al[mt], bh[nt]);
                    mma_bf16(acc[mt][nt], ah[mt], bl[nt]);
                }
        }
    }
}

// ------------------------- QKV GEMM (mma.sync bf16x3) -> bf16 hi/lo q/k/v -------------------------
__global__ __launch_bounds__(256, 1) void qkv_mma_kernel() {
    extern __shared__ __align__(16) char smem[];
    int b = blockIdx.z, m0 = blockIdx.x * 128, n0 = blockIdx.y * 128;

    float acc[4][4][4];
#pragma unroll
    for (int i = 0; i < 4; i++)
#pragma unroll
        for (int j = 0; j < 4; j++)
#pragma unroll
            for (int r = 0; r < 4; r++) acc[i][j][r] = 0.f;

    gemm_bf16x3_acc(d_thi + ((size_t)b*Nn + m0)*Cc, d_tlo + ((size_t)b*Nn + m0)*Cc,
                    d_whi + (size_t)n0*Cc,          d_wlo + (size_t)n0*Cc,
                    smem, acc);

    const int tid = threadIdx.x, w = tid >> 5, l = tid & 31;
    const int mb = (w >> 2) * 64, nb = (w & 3) * 32;
    const int trow = l >> 2, tcol = (l & 3) * 2;
    const int sec = n0 >> 9;     // 0=q 1=k 2=v
    const float mult = (sec == 0) ? SCALE : 1.f;

#pragma unroll
    for (int mt = 0; mt < 4; mt++) {
#pragma unroll
        for (int nt = 0; nt < 4; nt++) {
            int tok = m0 + mb + mt*16 + trow;
            int j   = n0 + nb + nt*8 + tcol;
            int jl  = j & 511;
            int hh  = jl >> 6, dd = jl & 63;
            int bh  = b*NH + hh;
            float* a4 = acc[mt][nt];
            if (sec == 2) {
#pragma unroll
                for (int e = 0; e < 4; e++) {
                    float v = a4[e];
                    int ddx = dd + (e & 1);
                    int tk  = NKV + tok + (e >> 1)*8;
                    bf16 h = __float2bfloat16(v);
                    size_t idx = ((size_t)bh*DH + ddx)*Lpad + tk;
                    d_vhi[idx] = h;
                    d_vlo[idx] = __float2bfloat16(v - __bfloat162float(h));
                }
            } else {
                bf16* ahp; bf16* alp; size_t ridx0, ridx1;
                if (sec == 0) {
                    ahp = d_qhi; alp = d_qlo;
                    ridx0 = ((size_t)bh*Nn + tok)*DH + dd;
                    ridx1 = ((size_t)bh*Nn + tok + 8)*DH + dd;
                } else {
                    ahp = d_khi; alp = d_klo;
                    ridx0 = ((size_t)bh*Lpad + NKV + tok)*DH + dd;
                    ridx1 = ((size_t)bh*Lpad + NKV + tok + 8)*DH + dd;
                }
                uint32_t h32, l32;
                split2(a4[0]*mult, a4[1]*mult, h32, l32);
                *(uint32_t*)(ahp + ridx0) = h32;
                *(uint32_t*)(alp + ridx0) = l32;
                split2(a4[2]*mult, a4[3]*mult, h32, l32);
                *(uint32_t*)(ahp + ridx1) = h32;
                *(uint32_t*)(alp + ridx1) = l32;
            }
        }
    }
}

// ------------------------- output projection GEMM + GN2 group partials -------------------------
__global__ __launch_bounds__(256, 1) void out_mma_kernel(const float* __restrict__ bout) {
    extern __shared__ __align__(16) char smem[];
    int b = blockIdx.z, m0 = blockIdx.x * 128, n0 = blockIdx.y * 128;

    float acc[4][4][4];
#pragma unroll
    for (int i = 0; i < 4; i++)
#pragma unroll
        for (int j = 0; j < 4; j++)
#pragma unroll
            for (int r = 0; r < 4; r++) acc[i][j][r] = 0.f;

    gemm_bf16x3_acc(d_ohi + ((size_t)b*Nn + m0)*HID, d_olo + ((size_t)b*Nn + m0)*HID,
                    d_wohi + (size_t)n0*HID,         d_wolo + (size_t)n0*HID,
                    smem, acc);

    const int tid = threadIdx.x, w = tid >> 5, l = tid & 31;
    const int mb = (w >> 2) * 64, nb = (w & 3) * 32;
    const int trow = l >> 2, tcol = (l & 3) * 2;

    float gsum[2] = {0.f, 0.f}, gsq[2] = {0.f, 0.f};

#pragma unroll
    for (int mt = 0; mt < 4; mt++) {
#pragma unroll
        for (int nt = 0; nt < 4; nt++) {
            int tok = m0 + mb + mt*16 + trow;
            int cc  = n0 + nb + nt*8 + tcol;
            float b0 = bout[cc], b1 = bout[cc+1];
            float* a4 = acc[mt][nt];
            float v0 = a4[0] + b0, v1 = a4[1] + b1;
            float v2 = a4[2] + b0, v3 = a4[3] + b1;
            d_y[((size_t)b*Cc + cc)*Nn + tok]       = v0;
            d_y[((size_t)b*Cc + cc+1)*Nn + tok]     = v1;
            d_y[((size_t)b*Cc + cc)*Nn + tok + 8]   = v2;
            d_y[((size_t)b*Cc + cc+1)*Nn + tok + 8] = v3;
            const int e = nt >> 1;
            gsum[e] += v0 + v1 + v2 + v3;
            gsq[e]  += v0*v0 + v1*v1 + v2*v2 + v3*v3;
        }
    }

#pragma unroll
    for (int off = 16; off; off >>= 1) {
        gsum[0] += __shfl_xor_sync(~0u, gsum[0], off);
        gsum[1] += __shfl_xor_sync(~0u, gsum[1], off);
        gsq[0]  += __shfl_xor_sync(~0u, gsq[0],  off);
        gsq[1]  += __shfl_xor_sync(~0u, gsq[1],  off);
    }
    __shared__ float sm_w[8][2][2];
    if (l == 0) {
        sm_w[w][0][0] = gsum[0]; sm_w[w][0][1] = gsq[0];
        sm_w[w][1][0] = gsum[1]; sm_w[w][1][1] = gsq[1];
    }
    __syncthreads();
    if (tid < 16) {
        int gg = tid >> 1, j = tid & 1;
        int p = gg >> 1, e = gg & 1;
        float v = sm_w[p][e][j] + sm_w[4 + p][e][j];
        int cta = (b*OUT_NY + blockIdx.y)*OUT_NX + blockIdx.x;
        d_part[(cta*8 + gg)*2 + j] = v;
    }
}

// ------------------------- GN2 finalize: partials -> per-channel affine -------------------------
__global__ void gn2_finalize_kernel(const float* __restrict__ w,
                                    const float* __restrict__ bgn) {
    int t = threadIdx.x;            // 64 = Bb*Gg
    int b = t >> 5, g = t & 31;
    int ny = g >> 3, gg = g & 7;
    float s = 0.f, q = 0.f;
    for (int nx = 0; nx < OUT_NX; nx++) {
        int cta = (b*OUT_NY + ny)*OUT_NX + nx;
        s += d_part[(cta*8 + gg)*2 + 0];
        q += d_part[(cta*8 + gg)*2 + 1];
    }
    float inv = 1.f / (float)(CG*Nn);
    float mu = s * inv;
    float var = q * inv - mu*mu;
    float rs = rsqrtf(var + 1e-5f);
#pragma unroll
    for (int i = 0; i < CG; i++) {
        int c = g*CG + i;
        float sc = rs * w[c];
        d_s2[b*Cc + c] = sc;
        d_b2[b*Cc + c] = bgn[c] - mu*sc;
    }
}

// ------------------------- Flash attention: KT=64 tiles, 96KB smem, 2 CTAs/SM -------------------------
// smem: buf A @0 (32K): [KH 8K | KL 8K | VH 8K | VL 8K]
//       buf B @32K: same layout; initially Q [QH 16K | QL 16K] (reused after frag load)
//       P @64K: [PH 16K | PL 16K].  total 96K.
#define FK_H 0u
#define FK_L 8192u
#define FV_H 16384u
#define FV_L 24576u
#define F_BUF(b) ((uint32_t)(b)*32768u)
#define F2_QH 32768u
#define F2_QL 49152u
#define F2_PH 65536u
#define F2_PL 81920u
#define FLASH_SMEM_BYTES 98304

__device__ __forceinline__ void flash_prefetch(uint32_t sb, int bh, int kt, uint32_t bufb, int tid) {
    const bf16* kh_g = d_khi + ((size_t)bh*Lpad + kt*KT2)*DH;
    const bf16* kl_g = d_klo + ((size_t)bh*Lpad + kt*KT2)*DH;
#pragma unroll
    for (int i = 0; i < 2; i++) {
        int idx = tid + i*256;
        int row = idx >> 3, u = idx & 7;
        uint32_t so = SW128B((uint32_t)row*128u + (uint32_t)u*16u);
        cpa16(sb + bufb + FK_H + so, kh_g + (size_t)row*DH + u*8);
        cpa16(sb + bufb + FK_L + so, kl_g + (size_t)row*DH + u*8);
    }
    const bf16* vh_g = d_vhi + (size_t)bh*DH*Lpad + kt*KT2;
    const bf16* vl_g = d_vlo + (size_t)bh*DH*Lpad + kt*KT2;
#pragma unroll
    for (int i = 0; i < 2; i++) {
        int idx = tid + i*256;
        int dd = idx >> 3, u = idx & 7;
        uint32_t so = SW128B((uint32_t)dd*128u + (uint32_t)u*16u);
        cpa16(sb + bufb + FV_H + so, vh_g + (size_t)dd*Lpad + u*8);
        cpa16(sb + bufb + FV_L + so, vl_g + (size_t)dd*Lpad + u*8);
    }
}

__global__ __launch_bounds__(256, 2) void flash_mma_kernel() {
    extern __shared__ __align__(16) char smem[];
    const uint32_t sb = smem_u32_of(smem);
    const int qt = blockIdx.x, h = blockIdx.y, b = blockIdx.z;
    const int bh = b*NH + h;
    const int tid = threadIdx.x, w = tid >> 5, l = tid & 31;
    const int trow = l >> 2, tcol = (l & 3) * 2;

    // ---- prologue: Q (into buf B region) + tile0 (buf A) via cp.async ----
    const bf16* qh_g = d_qhi + ((size_t)bh*Nn + qt*128)*DH;
    const bf16* ql_g = d_qlo + ((size_t)bh*Nn + qt*128)*DH;
#pragma unroll
    for (int i = 0; i < 4; i++) {
        int idx = tid + i*256;
        int row = idx >> 3, u = idx & 7;
        uint32_t so = SW128B((uint32_t)row*128u + (uint32_t)u*16u);
        cpa16(sb + F2_QH + so, qh_g + (size_t)row*DH + u*8);
        cpa16(sb + F2_QL + so, ql_g + (size_t)row*DH + u*8);
    }
    flash_prefetch(sb, bh, 0, F_BUF(0), tid);
    CP_COMMIT();
    CP_WAIT0();
    __syncthreads();

    const int arow = (l & 7) + ((l >> 3) & 1) * 8;
    const int acol = (l & 16) ? 16 : 0;
    const int xrow = ((l >> 4) & 1) * 8 + (l & 7);
    const int xcol = ((l >> 3) & 1) * 16;
    uint32_t qfh[4][4], qfl[4][4];
#pragma unroll
    for (int ks = 0; ks < 4; ks++) {
        uint32_t off = SW128B((uint32_t)(w*16 + arow)*128u + ks*32 + acol);
        ldm_x4(qfh[ks], sb + F2_QH + off);
        ldm_x4(qfl[ks], sb + F2_QL + off);
    }
    __syncthreads();   // Q region free for reuse as buf B

    float mrow[2] = {-1e30f, -1e30f};
    float lrow[2] = {0.f, 0.f};
    float oacc[8][4];
#pragma unroll
    for (int nt = 0; nt < 8; nt++)
#pragma unroll
        for (int r = 0; r < 4; r++) oacc[nt][r] = 0.f;

    for (int kt = 0; kt < NKT2; kt++) {
        const uint32_t bufb = F_BUF(kt & 1);
        const bool tail = (kt == NKT2 - 1);
        if (kt + 1 < NKT2) {
            flash_prefetch(sb, bh, kt + 1, F_BUF((kt + 1) & 1), tid);
            CP_COMMIT();
        }

        // ---- S = Q K^T (8 n-tiles of 8 keys = 4 x4-pairs; tail computes pair 0 only) ----
        float sacc[8][4];
#pragma unroll
        for (int nt = 0; nt < 8; nt++)
#pragma unroll
            for (int r = 0; r < 4; r++) sacc[nt][r] = 0.f;

#pragma unroll
        for (int ks = 0; ks < 4; ks++) {
#pragma unroll
            for (int nt2 = 0; nt2 < 4; nt2++) {
                if (nt2 == 0 || !tail) {
                    uint32_t off = SW128B((uint32_t)(nt2*16 + xrow)*128u + ks*32 + xcol);
                    uint32_t kh4[4], kl4[4];
                    ldm_x4(kh4, sb + bufb + FK_H + off);
                    ldm_x4(kl4, sb + bufb + FK_L + off);
                    mma_bf16(sacc[2*nt2],   qfh[ks], kh4);
                    mma_bf16(sacc[2*nt2],   qfl[ks], kh4);
                    mma_bf16(sacc[2*nt2],   qfh[ks], kl4);
                    mma_bf16(sacc[2*nt2+1], qfh[ks], kh4+2);
                    mma_bf16(sacc[2*nt2+1], qfl[ks], kh4+2);
                    mma_bf16(sacc[2*nt2+1], qfh[ks], kl4+2);
                }
            }
        }

        // ---- mask tail tile ----
        if (tail) {
#pragma unroll
            for (int nt = 0; nt < 8; nt++) {
                int k0i = (NKT2-1)*KT2 + nt*8 + tcol;
                if (k0i >= Ltot)     { sacc[nt][0] = -1e30f; sacc[nt][2] = -1e30f; }
                if (k0i + 1 >= Ltot) { sacc[nt][1] = -1e30f; sacc[nt][3] = -1e30f; }
            }
        }

        // ---- online softmax ----
#pragma unroll
        for (int r = 0; r < 2; r++) {
            int ro = 2*r;
            float rm = -1e30f;
#pragma unroll
            for (int nt = 0; nt < 8; nt++)
                rm = fmaxf(rm, fmaxf(sacc[nt][ro], sacc[nt][ro+1]));
            rm = fmaxf(rm, __shfl_xor_sync(~0u, rm, 1, 4));
            rm = fmaxf(rm, __shfl_xor_sync(~0u, rm, 2, 4));
            float mn = fmaxf(mrow[r], rm);
            float alpha = __expf(mrow[r] - mn);
            mrow[r] = mn;
            float rs = 0.f;
#pragma unroll
            for (int nt = 0; nt < 8; nt++) {
                float p0 = __expf(sacc[nt][ro]   - mn);
                float p1 = __expf(sacc[nt][ro+1] - mn);
                sacc[nt][ro] = p0; sacc[nt][ro+1] = p1;
                rs += p0 + p1;
            }
            rs += __shfl_xor_sync(~0u, rs, 1, 4);
            rs += __shfl_xor_sync(~0u, rs, 2, 4);
            lrow[r] = lrow[r]*alpha + rs;
#pragma unroll
            for (int nt = 0; nt < 8; nt++) {
                oacc[nt][ro] *= alpha; oacc[nt][ro+1] *= alpha;
            }
        }

        // ---- write P hi/lo to smem [128 q][64 tok] (warp-private rows) ----
#pragma unroll
        for (int nt = 0; nt < 8; nt++) {
            int col = nt*8 + tcol;
            uint32_t bc = (uint32_t)col * 2u;
            uint32_t h32, l32;
            split2(sacc[nt][0], sacc[nt][1], h32, l32);
            uint32_t o0 = SW128B((uint32_t)(w*16 + trow)*128u + bc);
            *(uint32_t*)(smem + F2_PH + o0) = h32;
            *(uint32_t*)(smem + F2_PL + o0) = l32;
            split2(sacc[nt][2], sacc[nt][3], h32, l32);
            uint32_t o1 = SW128B((uint32_t)(w*16 + trow + 8)*128u + bc);
            *(uint32_t*)(smem + F2_PH + o1) = h32;
            *(uint32_t*)(smem + F2_PL + o1) = l32;
        }
        __syncwarp();

        // ---- O += P V (4 k-steps of 16; tail uses only ks2=0) ----
#pragma unroll
        for (int ks2 = 0; ks2 < 4; ks2++) {
            if (ks2 == 0 || !tail) {
                uint32_t kb = (uint32_t)ks2 * 32u;
                uint32_t pfh[4], pfl[4];
                uint32_t offA = SW128B((uint32_t)(w*16 + arow)*128u + kb + acol);
                ldm_x4(pfh, sb + F2_PH + offA);
                ldm_x4(pfl, sb + F2_PL + offA);
#pragma unroll
                for (int nt2 = 0; nt2 < 4; nt2++) {
                    uint32_t offB = SW128B((uint32_t)(nt2*16 + xrow)*128u + kb + xcol);
                    uint32_t vh4[4], vl4[4];
                    ldm_x4(vh4, sb + bufb + FV_H + offB);
                    ldm_x4(vl4, sb + bufb + FV_L + offB);
                    mma_bf16(oacc[2*nt2],   pfh, vh4);
                    mma_bf16(oacc[2*nt2],   pfl, vh4);
                    mma_bf16(oacc[2*nt2],   pfh, vl4);
                    mma_bf16(oacc[2*nt2+1], pfh, vh4+2);
                    mma_bf16(oacc[2*nt2+1], pfl, vh4+2);
                    mma_bf16(oacc[2*nt2+1], pfh, vl4+2);
                }
            }
        }

        if (kt + 1 < NKT2) {
            CP_WAIT0();
            __syncthreads();
        }
    }

    // ---- epilogue ----
#pragma unroll
    for (int r = 0; r < 2; r++) {
        float inv = 1.f / lrow[r];
        int tok = qt*128 + w*16 + trow + r*8;
        size_t rowb = (size_t)(b*Nn + tok)*HID + h*DH;
#pragma unroll
        for (int nt = 0; nt < 8; nt++) {
            uint32_t h32, l32;
            split2(oacc[nt][2*r]*inv, oacc[nt][2*r+1]*inv, h32, l32);
            int col = nt*8 + tcol;
            *(uint32_t*)(d_ohi + rowb + col) = h32;
            *(uint32_t*)(d_olo + rowb + col) = l32;
        }
    }
}

// ------------------------- GN2 apply -> final output -------------------------
__global__ void gn_apply_kernel(float* __restrict__ out) {
    int f = blockIdx.x * 256 + threadIdx.x;
    float4 v = ((const float4*)d_y)[f];
    int bc = f / (Nn/4);
    float s = d_s2[bc], bb = d_b2[bc];
    float4 r;
    r.x = v.x*s + bb; r.y = v.y*s + bb; r.z = v.z*s + bb; r.w = v.w*s + bb;
    ((float4*)out)[f] = r;
}

// ------------------------- launch -------------------------
extern "C" void kernel_launch(void* const* d_in, const int* in_sizes, int n_in,
                              void* d_out, int out_size) {
    const float* x     = (const float*)d_in[0];
    const float* gn1_w = (const float*)d_in[1];
    const float* gn1_b = (const float*)d_in[2];
    const float* w_qkv = (const float*)d_in[3];
    const float* memkv = (const float*)d_in[4];
    const float* w_out = (const float*)d_in[5];
    const float* b_out = (const float*)d_in[6];
    const float* gn2_w = (const float*)d_in[7];
    const float* gn2_b = (const float*)d_in[8];
    float* out = (float*)d_out;

    static bool attr_set = false;
    if (!attr_set) {
        cudaFuncSetAttribute(flash_mma_kernel, cudaFuncAttributeMaxDynamicSharedMemorySize, FLASH_SMEM_BYTES);
        cudaFuncSetAttribute(qkv_mma_kernel,   cudaFuncAttributeMaxDynamicSharedMemorySize, GEMM_SMEM_BYTES);
        cudaFuncSetAttribute(out_mma_kernel,   cudaFuncAttributeMaxDynamicSharedMemorySize, GEMM_SMEM_BYTES);
        attr_set = true;
    }

    float *p_s1, *p_b1;
    cudaGetSymbolAddress((void**)&p_s1, d_s1);
    cudaGetSymbolAddress((void**)&p_b1, d_b1);

    gn_stats_kernel<<<Bb*Gg, 256>>>(x, gn1_w, gn1_b, p_s1, p_b1);
    prep_misc_kernel<<<SPLIT_TOTAL + Bb*NH*8, 256>>>(w_qkv, w_out, memkv);
    prep_x_kernel<<<dim3(Nn/32, Cc/32, Bb), 256>>>(x);
    qkv_mma_kernel<<<dim3(Nn/128, QKVJ/128, Bb), 256, GEMM_SMEM_BYTES>>>();
    flash_mma_kernel<<<dim3(Nn/128, NH, Bb), 256, FLASH_SMEM_BYTES>>>();
    out_mma_kernel<<<dim3(OUT_NX, OUT_NY, Bb), 256, GEMM_SMEM_BYTES>>>(b_out);
    gn2_finalize_kernel<<<1, 64>>>(gn2_w, gn2_b);
    gn_apply_kernel<<<(Bb*Cc*Nn/4)/256, 256>>>(out);
}

// round 17
// speedup vs baseline: 1.0196x; 1.0067x over previous
#include <cuda_runtime.h>
#include <cuda_bf16.h>
#include <cstdint>

#define Bb   2
#define Cc   512
#define Nn   2304          // 48*48
#define Gg   32
#define CG   16            // Cc/Gg
#define NH   8
#define DH   64
#define HID  512
#define QKVJ 1536
#define NKV  4
#define Ltot 2308          // Nn + NKV
#define Lpad 2368          // 37*64
#define KT2  64
#define NKT2 37
#define SCALE 0.125f       // DH^-0.5
#define OUT_NX 18          // Nn/128
#define OUT_NY 4           // HID/128

typedef unsigned long long u64;
typedef __nv_bfloat16 bf16;

// byte swizzle for 128-byte rows (mma smem tiles)
#define SW128B(o) ((o) ^ (((o) >> 3) & 0x70))

// ---------- mma.sync helpers ----------
__device__ __forceinline__ uint32_t smem_u32_of(const void* p) {
    uint32_t a;
    asm("{ .reg .u64 t; cvta.to.shared.u64 t, %1; cvt.u32.u64 %0, t; }" : "=r"(a) : "l"(p));
    return a;
}
__device__ __forceinline__ void ldm_x4(uint32_t r[4], uint32_t a) {
    asm volatile("ldmatrix.sync.aligned.m8n8.x4.shared.b16 {%0,%1,%2,%3}, [%4];"
        : "=r"(r[0]), "=r"(r[1]), "=r"(r[2]), "=r"(r[3]) : "r"(a));
}
__device__ __forceinline__ void ldm_x2(uint32_t r[2], uint32_t a) {
    asm volatile("ldmatrix.sync.aligned.m8n8.x2.shared.b16 {%0,%1}, [%2];"
        : "=r"(r[0]), "=r"(r[1]) : "r"(a));
}
__device__ __forceinline__ void mma_bf16(float d[4], const uint32_t a[4], const uint32_t b[2]) {
    asm volatile(
        "mma.sync.aligned.m16n8k16.row.col.f32.bf16.bf16.f32 "
        "{%0,%1,%2,%3}, {%4,%5,%6,%7}, {%8,%9}, {%0,%1,%2,%3};"
        : "+f"(d[0]), "+f"(d[1]), "+f"(d[2]), "+f"(d[3])
        : "r"(a[0]), "r"(a[1]), "r"(a[2]), "r"(a[3]), "r"(b[0]), "r"(b[1]));
}
__device__ __forceinline__ void cpa16(uint32_t s, const void* g) {
    asm volatile("cp.async.cg.shared.global [%0], [%1], 16;" :: "r"(s), "l"(g));
}
#define CP_COMMIT() asm volatile("cp.async.commit_group;" ::: "memory")
#define CP_WAIT0()  asm volatile("cp.async.wait_group 0;" ::: "memory")

// pack two floats to bf16x2 hi + residual lo
__device__ __forceinline__ void split2(float a, float b, uint32_t& hi, uint32_t& lo) {
    __nv_bfloat162 h, l2;
    h.x = __float2bfloat16(a); h.y = __float2bfloat16(b);
    l2.x = __float2bfloat16(a - __bfloat162float(h.x));
    l2.y = __float2bfloat16(b - __bfloat162float(h.y));
    hi = *(uint32_t*)&h; lo = *(uint32_t*)&l2;
}

// ------------------------- scratch (device globals) -------------------------
__device__ float d_s1[Bb*Cc], d_b1[Bb*Cc], d_s2[Bb*Cc], d_b2[Bb*Cc];
__device__ bf16 d_thi[(size_t)Bb*Nn*Cc],  d_tlo[(size_t)Bb*Nn*Cc];   // tokens [b][tok][c]
__device__ bf16 d_whi[(size_t)QKVJ*Cc],   d_wlo[(size_t)QKVJ*Cc];    // w_qkv  [j][c]
__device__ bf16 d_wohi[(size_t)Cc*HID],   d_wolo[(size_t)Cc*HID];    // w_out  [c][j]
__device__ bf16 d_qhi[(size_t)Bb*NH*Nn*DH],   d_qlo[(size_t)Bb*NH*Nn*DH];    // [b,h][tok][d] prescaled
__device__ bf16 d_khi[(size_t)Bb*NH*Lpad*DH], d_klo[(size_t)Bb*NH*Lpad*DH];  // [b,h][tok][d]
__device__ bf16 d_vhi[(size_t)Bb*NH*DH*Lpad], d_vlo[(size_t)Bb*NH*DH*Lpad];  // [b,h][d][tok]
__device__ bf16 d_ohi[(size_t)Bb*Nn*HID], d_olo[(size_t)Bb*Nn*HID];  // attn out [b][tok][j]
__device__ float d_y[(size_t)Bb*Cc*Nn];
__device__ float d_part[Bb*OUT_NY*OUT_NX*8*2];   // GN2 per-CTA group partials (sum, sumsq)

// ------------------------- GroupNorm stats -> affine (input GN) -------------------------
__global__ void gn_stats_kernel(const float* __restrict__ src,
                                const float* __restrict__ w,
                                const float* __restrict__ bgn,
                                float* __restrict__ sout,
                                float* __restrict__ bout) {
    int b = blockIdx.x >> 5;
    int g = blockIdx.x & 31;
    const float* p = src + ((size_t)b*Cc + g*CG) * Nn;
    float sum = 0.f, sq = 0.f;
    for (int i = threadIdx.x; i < CG*Nn; i += 256) {
        float v = p[i]; sum += v; sq += v*v;
    }
    __shared__ float r0[8], r1[8];
    __shared__ float smu, srs;
    int lane = threadIdx.x & 31, wid = threadIdx.x >> 5;
#pragma unroll
    for (int off = 16; off; off >>= 1) {
        sum += __shfl_xor_sync(~0u, sum, off);
        sq  += __shfl_xor_sync(~0u, sq,  off);
    }
    if (!lane) { r0[wid] = sum; r1[wid] = sq; }
    __syncthreads();
    if (threadIdx.x == 0) {
        float s = 0.f, q = 0.f;
#pragma unroll
        for (int i = 0; i < 8; i++) { s += r0[i]; q += r1[i]; }
        float inv = 1.f / (float)(CG*Nn);
        float mu  = s * inv;
        float var = q * inv - mu*mu;
        smu = mu; srs = rsqrtf(var + 1e-5f);
    }
    __syncthreads();
    if (threadIdx.x < CG) {
        int c = g*CG + threadIdx.x;
        float ww = w[c];
        float sc = srs * ww;
        sout[b*Cc + c] = sc;
        bout[b*Cc + c] = bgn[c] - smu * sc;
    }
}

// ------------------------- prep: transpose x + GN1 affine + bf16 split -------------------------
__global__ void prep_x_kernel(const float* __restrict__ x) {
    __shared__ float t[32][33];
    int b = blockIdx.z;
    int c0 = blockIdx.y * 32;
    int t0 = blockIdx.x * 32;
    int lx = threadIdx.x & 31, ly = threadIdx.x >> 5;
#pragma unroll
    for (int i = 0; i < 4; i++) {
        int c = c0 + ly + i*8;
        float v = x[((size_t)b*Cc + c)*Nn + t0 + lx];
        t[ly + i*8][lx] = v * d_s1[b*Cc + c] + d_b1[b*Cc + c];
    }
    __syncthreads();
#pragma unroll
    for (int i = 0; i < 4; i++) {
        int tok = t0 + ly + i*8;
        int c = c0 + lx;
        float v = t[lx][ly + i*8];
        bf16 hi = __float2bfloat16(v);
        bf16 lo = __float2bfloat16(v - __bfloat162float(hi));
        size_t idx = ((size_t)b*Nn + tok)*Cc + c;
        d_thi[idx] = hi; d_tlo[idx] = lo;
    }
}

// ------------------------- prep: weight splits + memkv prepend, one launch -------------------------
#define SPLIT1_BLOCKS ((QKVJ*Cc)/256)
#define SPLIT2_BLOCKS ((Cc*HID)/256)
#define SPLIT_TOTAL   (SPLIT1_BLOCKS + SPLIT2_BLOCKS)
#define PADT (Lpad - Ltot)    // 60
__global__ void prep_misc_kernel(const float* __restrict__ w_qkv,
                                 const float* __restrict__ w_out,
                                 const float* __restrict__ mem) {
    int blk = blockIdx.x;
    int t = threadIdx.x;
    if (blk < SPLIT_TOTAL) {
        const float* src; bf16 *hi, *lo; int i;
        if (blk < SPLIT1_BLOCKS) {
            src = w_qkv; hi = d_whi; lo = d_wlo;
            i = blk * 256 + t;
        } else {
            src = w_out; hi = d_wohi; lo = d_wolo;
            i = (blk - SPLIT1_BLOCKS) * 256 + t;
        }
        float v = src[i];
        bf16 h = __float2bfloat16(v);
        hi[i] = h;
        lo[i] = __float2bfloat16(v - __bfloat162float(h));
        return;
    }
    // memkv part
    int mblk = blk - SPLIT_TOTAL;
    int bh = mblk >> 3, part = mblk & 7;
    int h = bh & 7, b = bh >> 3;
    const bf16 z = __float2bfloat16(0.f);

    if (part == 0) {
        int l = t >> 6, d = t & 63;
        float kv = mem[((size_t)h*DH + d)*NKV + l];
        float vv = mem[((size_t)(NH + h)*DH + d)*NKV + l];
        bf16 kh = __float2bfloat16(kv);
        bf16 vh = __float2bfloat16(vv);
        size_t ki = ((size_t)bh*Lpad + l)*DH + d;
        size_t vi = ((size_t)bh*DH + d)*Lpad + l;
        d_khi[ki] = kh; d_klo[ki] = __float2bfloat16(kv - __bfloat162float(kh));
        d_vhi[vi] = vh; d_vlo[vi] = __float2bfloat16(vv - __bfloat162float(vh));
    }
    if (part < 4) {
        int seg = part;
        for (int i = t; i < 15*DH; i += 256) {
            int r = seg*15 + i / DH, d = i % DH;
            size_t ki = ((size_t)bh*Lpad + Ltot + r)*DH + d;
            d_khi[ki] = z; d_klo[ki] = z;
        }
    } else {
        int seg = part & 3;
        for (int i = t; i < 16*PADT; i += 256) {
            int d = seg*16 + i / PADT, off = i % PADT;
            size_t vi = ((size_t)bh*DH + d)*Lpad + Ltot + off;
            d_vhi[vi] = z; d_vlo[vi] = z;
        }
    }
}

// ------------------------- bf16x3 mma.sync mainloop (low-reg variant, 2 CTAs/SM) -----------------
// Per k-step: load all B fragments (16 regs), then per mt load one A pair (8 regs) + 12 MMAs.
#define SA_HI 0u
#define SA_LO 16384u
#define SB_HI 32768u
#define SB_LO 49152u
#define GEMM_SMEM_BYTES 65536

__device__ __forceinline__ void gemm_bf16x3_acc(
    const bf16* __restrict__ Ahi, const bf16* __restrict__ Alo,
    const bf16* __restrict__ Bhi, const bf16* __restrict__ Blo,
    char* smem, float acc[4][4][4])
{
    const int tid = threadIdx.x;
    const int w = tid >> 5, l = tid & 31;
    const int mb = (w >> 2) * 64, nb = (w & 3) * 32;
    const uint32_t sbase = smem_u32_of(smem);

    const int arow = (l & 7) + ((l >> 3) & 1) * 8;
    const int acol = (l & 16) ? 16 : 0;
    const int brow = l & 7;
    const int bcol = (l & 8) ? 16 : 0;

    const bf16* srcs[4] = {Ahi, Alo, Bhi, Blo};

    for (int ch = 0; ch < 8; ch++) {
        if (ch) __syncthreads();
        int k0 = ch * 64;
#pragma unroll
        for (int tI = 0; tI < 4; tI++) {
            const char* src = (const char*)srcs[tI] + k0*2;
            uint32_t tb = tI * 16384u;
#pragma unroll
            for (int it = 0; it < 4; it++) {
                int idx = tid + it*256;
                int row = idx >> 3, u = idx & 7;
                uint4 v = *(const uint4*)(src + (size_t)row*1024 + u*16);
                uint32_t boff = (uint32_t)row*128u + (uint32_t)u*16u;
                *(uint4*)(smem + tb + SW128B(boff)) = v;
            }
        }
        __syncthreads();

#pragma unroll
        for (int ks = 0; ks < 4; ks++) {
            int kb = ks * 32;
            uint32_t bh[4][2], bl[4][2];
#pragma unroll
            for (int nt = 0; nt < 4; nt++) {
                uint32_t off = SW128B((uint32_t)(nb + nt*8 + brow)*128u + kb + bcol);
                ldm_x2(bh[nt], sbase + SB_HI + off);
                ldm_x2(bl[nt], sbase + SB_LO + off);
            }
#pragma unroll
            for (int mt = 0; mt < 4; mt++) {
                uint32_t ah[4], al[4];
                uint32_t off = SW128B((uint32_t)(mb + mt*16 + arow)*128u + kb + acol);
                ldm_x4(ah, sbase + SA_HI + off);
                ldm_x4(al, sbase + SA_LO + off);
#pragma unroll
                for (int nt = 0; nt < 4; nt++) {
                    mma_bf16(acc[mt][nt], ah, bh[nt]);
                    mma_bf16(acc[mt][nt], al, bh[nt]);
                    mma_bf16(acc[mt][nt], ah, bl[nt]);
                }
            }
        }
    }
}

// ------------------------- QKV GEMM (mma.sync bf16x3) -> bf16 hi/lo q/k/v -------------------------
__global__ __launch_bounds__(256, 2) void qkv_mma_kernel() {
    extern __shared__ __align__(16) char smem[];
    int b = blockIdx.z, m0 = blockIdx.x * 128, n0 = blockIdx.y * 128;

    float acc[4][4][4];
#pragma unroll
    for (int i = 0; i < 4; i++)
#pragma unroll
        for (int j = 0; j < 4; j++)
#pragma unroll
            for (int r = 0; r < 4; r++) acc[i][j][r] = 0.f;

    gemm_bf16x3_acc(d_thi + ((size_t)b*Nn + m0)*Cc, d_tlo + ((size_t)b*Nn + m0)*Cc,
                    d_whi + (size_t)n0*Cc,          d_wlo + (size_t)n0*Cc,
                    smem, acc);

    const int tid = threadIdx.x, w = tid >> 5, l = tid & 31;
    const int mb = (w >> 2) * 64, nb = (w & 3) * 32;
    const int trow = l >> 2, tcol = (l & 3) * 2;
    const int sec = n0 >> 9;     // 0=q 1=k 2=v
    const float mult = (sec == 0) ? SCALE : 1.f;

#pragma unroll
    for (int mt = 0; mt < 4; mt++) {
#pragma unroll
        for (int nt = 0; nt < 4; nt++) {
            int tok = m0 + mb + mt*16 + trow;
            int j   = n0 + nb + nt*8 + tcol;
            int jl  = j & 511;
            int hh  = jl >> 6, dd = jl & 63;
            int bh  = b*NH + hh;
            float* a4 = acc[mt][nt];
            if (sec == 2) {
#pragma unroll
                for (int e = 0; e < 4; e++) {
                    float v = a4[e];
                    int ddx = dd + (e & 1);
                    int tk  = NKV + tok + (e >> 1)*8;
                    bf16 h = __float2bfloat16(v);
                    size_t idx = ((size_t)bh*DH + ddx)*Lpad + tk;
                    d_vhi[idx] = h;
                    d_vlo[idx] = __float2bfloat16(v - __bfloat162float(h));
                }
            } else {
                bf16* ahp; bf16* alp; size_t ridx0, ridx1;
                if (sec == 0) {
                    ahp = d_qhi; alp = d_qlo;
                    ridx0 = ((size_t)bh*Nn + tok)*DH + dd;
                    ridx1 = ((size_t)bh*Nn + tok + 8)*DH + dd;
                } else {
                    ahp = d_khi; alp = d_klo;
                    ridx0 = ((size_t)bh*Lpad + NKV + tok)*DH + dd;
                    ridx1 = ((size_t)bh*Lpad + NKV + tok + 8)*DH + dd;
                }
                uint32_t h32, l32;
                split2(a4[0]*mult, a4[1]*mult, h32, l32);
                *(uint32_t*)(ahp + ridx0) = h32;
                *(uint32_t*)(alp + ridx0) = l32;
                split2(a4[2]*mult, a4[3]*mult, h32, l32);
                *(uint32_t*)(ahp + ridx1) = h32;
                *(uint32_t*)(alp + ridx1) = l32;
            }
        }
    }
}

// ------------------------- output projection GEMM + GN2 group partials -------------------------
__global__ __launch_bounds__(256, 2) void out_mma_kernel(const float* __restrict__ bout) {
    extern __shared__ __align__(16) char smem[];
    int b = blockIdx.z, m0 = blockIdx.x * 128, n0 = blockIdx.y * 128;

    float acc[4][4][4];
#pragma unroll
    for (int i = 0; i < 4; i++)
#pragma unroll
        for (int j = 0; j < 4; j++)
#pragma unroll
            for (int r = 0; r < 4; r++) acc[i][j][r] = 0.f;

    gemm_bf16x3_acc(d_ohi + ((size_t)b*Nn + m0)*HID, d_olo + ((size_t)b*Nn + m0)*HID,
                    d_wohi + (size_t)n0*HID,         d_wolo + (size_t)n0*HID,
                    smem, acc);

    const int tid = threadIdx.x, w = tid >> 5, l = tid & 31;
    const int mb = (w >> 2) * 64, nb = (w & 3) * 32;
    const int trow = l >> 2, tcol = (l & 3) * 2;

    float gsum[2] = {0.f, 0.f}, gsq[2] = {0.f, 0.f};

#pragma unroll
    for (int mt = 0; mt < 4; mt++) {
#pragma unroll
        for (int nt = 0; nt < 4; nt++) {
            int tok = m0 + mb + mt*16 + trow;
            int cc  = n0 + nb + nt*8 + tcol;
            float b0 = bout[cc], b1 = bout[cc+1];
            float* a4 = acc[mt][nt];
            float v0 = a4[0] + b0, v1 = a4[1] + b1;
            float v2 = a4[2] + b0, v3 = a4[3] + b1;
            d_y[((size_t)b*Cc + cc)*Nn + tok]       = v0;
            d_y[((size_t)b*Cc + cc+1)*Nn + tok]     = v1;
            d_y[((size_t)b*Cc + cc)*Nn + tok + 8]   = v2;
            d_y[((size_t)b*Cc + cc+1)*Nn + tok + 8] = v3;
            const int e = nt >> 1;
            gsum[e] += v0 + v1 + v2 + v3;
            gsq[e]  += v0*v0 + v1*v1 + v2*v2 + v3*v3;
        }
    }

#pragma unroll
    for (int off = 16; off; off >>= 1) {
        gsum[0] += __shfl_xor_sync(~0u, gsum[0], off);
        gsum[1] += __shfl_xor_sync(~0u, gsum[1], off);
        gsq[0]  += __shfl_xor_sync(~0u, gsq[0],  off);
        gsq[1]  += __shfl_xor_sync(~0u, gsq[1],  off);
    }
    __shared__ float sm_w[8][2][2];
    if (l == 0) {
        sm_w[w][0][0] = gsum[0]; sm_w[w][0][1] = gsq[0];
        sm_w[w][1][0] = gsum[1]; sm_w[w][1][1] = gsq[1];
    }
    __syncthreads();
    if (tid < 16) {
        int gg = tid >> 1, j = tid & 1;
        int p = gg >> 1, e = gg & 1;
        float v = sm_w[p][e][j] + sm_w[4 + p][e][j];
        int cta = (b*OUT_NY + blockIdx.y)*OUT_NX + blockIdx.x;
        d_part[(cta*8 + gg)*2 + j] = v;
    }
}

// ------------------------- GN2 finalize: partials -> per-channel affine -------------------------
__global__ void gn2_finalize_kernel(const float* __restrict__ w,
                                    const float* __restrict__ bgn) {
    int t = threadIdx.x;            // 64 = Bb*Gg
    int b = t >> 5, g = t & 31;
    int ny = g >> 3, gg = g & 7;
    float s = 0.f, q = 0.f;
    for (int nx = 0; nx < OUT_NX; nx++) {
        int cta = (b*OUT_NY + ny)*OUT_NX + nx;
        s += d_part[(cta*8 + gg)*2 + 0];
        q += d_part[(cta*8 + gg)*2 + 1];
    }
    float inv = 1.f / (float)(CG*Nn);
    float mu = s * inv;
    float var = q * inv - mu*mu;
    float rs = rsqrtf(var + 1e-5f);
#pragma unroll
    for (int i = 0; i < CG; i++) {
        int c = g*CG + i;
        float sc = rs * w[c];
        d_s2[b*Cc + c] = sc;
        d_b2[b*Cc + c] = bgn[c] - mu*sc;
    }
}

// ------------------------- Flash attention: KT=64 tiles, 96KB smem, 2 CTAs/SM -------------------------
#define FK_H 0u
#define FK_L 8192u
#define FV_H 16384u
#define FV_L 24576u
#define F_BUF(b) ((uint32_t)(b)*32768u)
#define F2_QH 32768u
#define F2_QL 49152u
#define F2_PH 65536u
#define F2_PL 81920u
#define FLASH_SMEM_BYTES 98304

__device__ __forceinline__ void flash_prefetch(uint32_t sb, int bh, int kt, uint32_t bufb, int tid) {
    const bf16* kh_g = d_khi + ((size_t)bh*Lpad + kt*KT2)*DH;
    const bf16* kl_g = d_klo + ((size_t)bh*Lpad + kt*KT2)*DH;
#pragma unroll
    for (int i = 0; i < 2; i++) {
        int idx = tid + i*256;
        int row = idx >> 3, u = idx & 7;
        uint32_t so = SW128B((uint32_t)row*128u + (uint32_t)u*16u);
        cpa16(sb + bufb + FK_H + so, kh_g + (size_t)row*DH + u*8);
        cpa16(sb + bufb + FK_L + so, kl_g + (size_t)row*DH + u*8);
    }
    const bf16* vh_g = d_vhi + (size_t)bh*DH*Lpad + kt*KT2;
    const bf16* vl_g = d_vlo + (size_t)bh*DH*Lpad + kt*KT2;
#pragma unroll
    for (int i = 0; i < 2; i++) {
        int idx = tid + i*256;
        int dd = idx >> 3, u = idx & 7;
        uint32_t so = SW128B((uint32_t)dd*128u + (uint32_t)u*16u);
        cpa16(sb + bufb + FV_H + so, vh_g + (size_t)dd*Lpad + u*8);
        cpa16(sb + bufb + FV_L + so, vl_g + (size_t)dd*Lpad + u*8);
    }
}

__global__ __launch_bounds__(256, 2) void flash_mma_kernel() {
    extern __shared__ __align__(16) char smem[];
    const uint32_t sb = smem_u32_of(smem);
    const int qt = blockIdx.x, h = blockIdx.y, b = blockIdx.z;
    const int bh = b*NH + h;
    const int tid = threadIdx.x, w = tid >> 5, l = tid & 31;
    const int trow = l >> 2, tcol = (l & 3) * 2;

    // ---- prologue: Q (into buf B region) + tile0 (buf A) via cp.async ----
    const bf16* qh_g = d_qhi + ((size_t)bh*Nn + qt*128)*DH;
    const bf16* ql_g = d_qlo + ((size_t)bh*Nn + qt*128)*DH;
#pragma unroll
    for (int i = 0; i < 4; i++) {
        int idx = tid + i*256;
        int row = idx >> 3, u = idx & 7;
        uint32_t so = SW128B((uint32_t)row*128u + (uint32_t)u*16u);
        cpa16(sb + F2_QH + so, qh_g + (size_t)row*DH + u*8);
        cpa16(sb + F2_QL + so, ql_g + (size_t)row*DH + u*8);
    }
    flash_prefetch(sb, bh, 0, F_BUF(0), tid);
    CP_COMMIT();
    CP_WAIT0();
    __syncthreads();

    const int arow = (l & 7) + ((l >> 3) & 1) * 8;
    const int acol = (l & 16) ? 16 : 0;
    const int xrow = ((l >> 4) & 1) * 8 + (l & 7);
    const int xcol = ((l >> 3) & 1) * 16;
    uint32_t qfh[4][4], qfl[4][4];
#pragma unroll
    for (int ks = 0; ks < 4; ks++) {
        uint32_t off = SW128B((uint32_t)(w*16 + arow)*128u + ks*32 + acol);
        ldm_x4(qfh[ks], sb + F2_QH + off);
        ldm_x4(qfl[ks], sb + F2_QL + off);
    }
    __syncthreads();   // Q region free for reuse as buf B

    float mrow[2] = {-1e30f, -1e30f};
    float lrow[2] = {0.f, 0.f};
    float oacc[8][4];
#pragma unroll
    for (int nt = 0; nt < 8; nt++)
#pragma unroll
        for (int r = 0; r < 4; r++) oacc[nt][r] = 0.f;

    for (int kt = 0; kt < NKT2; kt++) {
        const uint32_t bufb = F_BUF(kt & 1);
        const bool tail = (kt == NKT2 - 1);
        if (kt + 1 < NKT2) {
            flash_prefetch(sb, bh, kt + 1, F_BUF((kt + 1) & 1), tid);
            CP_COMMIT();
        }

        // ---- S = Q K^T (8 n-tiles of 8 keys = 4 x4-pairs; tail computes pair 0 only) ----
        float sacc[8][4];
#pragma unroll
        for (int nt = 0; nt < 8; nt++)
#pragma unroll
            for (int r = 0; r < 4; r++) sacc[nt][r] = 0.f;

#pragma unroll
        for (int ks = 0; ks < 4; ks++) {
#pragma unroll
            for (int nt2 = 0; nt2 < 4; nt2++) {
                if (nt2 == 0 || !tail) {
                    uint32_t off = SW128B((uint32_t)(nt2*16 + xrow)*128u + ks*32 + xcol);
                    uint32_t kh4[4], kl4[4];
                    ldm_x4(kh4, sb + bufb + FK_H + off);
                    ldm_x4(kl4, sb + bufb + FK_L + off);
                    mma_bf16(sacc[2*nt2],   qfh[ks], kh4);
                    mma_bf16(sacc[2*nt2],   qfl[ks], kh4);
                    mma_bf16(sacc[2*nt2],   qfh[ks], kl4);
                    mma_bf16(sacc[2*nt2+1], qfh[ks], kh4+2);
                    mma_bf16(sacc[2*nt2+1], qfl[ks], kh4+2);
                    mma_bf16(sacc[2*nt2+1], qfh[ks], kl4+2);
                }
            }
        }

        // ---- mask tail tile ----
        if (tail) {
#pragma unroll
            for (int nt = 0; nt < 8; nt++) {
                int k0i = (NKT2-1)*KT2 + nt*8 + tcol;
                if (k0i >= Ltot)     { sacc[nt][0] = -1e30f; sacc[nt][2] = -1e30f; }
                if (k0i + 1 >= Ltot) { sacc[nt][1] = -1e30f; sacc[nt][3] = -1e30f; }
            }
        }

        // ---- online softmax ----
#pragma unroll
        for (int r = 0; r < 2; r++) {
            int ro = 2*r;
            float rm = -1e30f;
#pragma unroll
            for (int nt = 0; nt < 8; nt++)
                rm = fmaxf(rm, fmaxf(sacc[nt][ro], sacc[nt][ro+1]));
            rm = fmaxf(rm, __shfl_xor_sync(~0u, rm, 1, 4));
            rm = fmaxf(rm, __shfl_xor_sync(~0u, rm, 2, 4));
            float mn = fmaxf(mrow[r], rm);
            float alpha = __expf(mrow[r] - mn);
            mrow[r] = mn;
            float rs = 0.f;
#pragma unroll
            for (int nt = 0; nt < 8; nt++) {
                float p0 = __expf(sacc[nt][ro]   - mn);
                float p1 = __expf(sacc[nt][ro+1] - mn);
                sacc[nt][ro] = p0; sacc[nt][ro+1] = p1;
                rs += p0 + p1;
            }
            rs += __shfl_xor_sync(~0u, rs, 1, 4);
            rs += __shfl_xor_sync(~0u, rs, 2, 4);
            lrow[r] = lrow[r]*alpha + rs;
#pragma unroll
            for (int nt = 0; nt < 8; nt++) {
                oacc[nt][ro] *= alpha; oacc[nt][ro+1] *= alpha;
            }
        }

        // ---- write P hi/lo to smem [128 q][64 tok] (warp-private rows) ----
#pragma unroll
        for (int nt = 0; nt < 8; nt++) {
            int col = nt*8 + tcol;
            uint32_t bc = (uint32_t)col * 2u;
            uint32_t h32, l32;
            split2(sacc[nt][0], sacc[nt][1], h32, l32);
            uint32_t o0 = SW128B((uint32_t)(w*16 + trow)*128u + bc);
            *(uint32_t*)(smem + F2_PH + o0) = h32;
            *(uint32_t*)(smem + F2_PL + o0) = l32;
            split2(sacc[nt][2], sacc[nt][3], h32, l32);
            uint32_t o1 = SW128B((uint32_t)(w*16 + trow + 8)*128u + bc);
            *(uint32_t*)(smem + F2_PH + o1) = h32;
            *(uint32_t*)(smem + F2_PL + o1) = l32;
        }
        __syncwarp();

        // ---- O += P V (4 k-steps of 16; tail uses only ks2=0) ----
#pragma unroll
        for (int ks2 = 0; ks2 < 4; ks2++) {
            if (ks2 == 0 || !tail) {
                uint32_t kb = (uint32_t)ks2 * 32u;
                uint32_t pfh[4], pfl[4];
                uint32_t offA = SW128B((uint32_t)(w*16 + arow)*128u + kb + acol);
                ldm_x4(pfh, sb + F2_PH + offA);
                ldm_x4(pfl, sb + F2_PL + offA);
#pragma unroll
                for (int nt2 = 0; nt2 < 4; nt2++) {
                    uint32_t offB = SW128B((uint32_t)(nt2*16 + xrow)*128u + kb + xcol);
                    uint32_t vh4[4], vl4[4];
                    ldm_x4(vh4, sb + bufb + FV_H + offB);
                    ldm_x4(vl4, sb + bufb + FV_L + offB);
                    mma_bf16(oacc[2*nt2],   pfh, vh4);
                    mma_bf16(oacc[2*nt2],   pfl, vh4);
                    mma_bf16(oacc[2*nt2],   pfh, vl4);
                    mma_bf16(oacc[2*nt2+1], pfh, vh4+2);
                    mma_bf16(oacc[2*nt2+1], pfl, vh4+2);
                    mma_bf16(oacc[2*nt2+1], pfh, vl4+2);
                }
            }
        }

        if (kt + 1 < NKT2) {
            CP_WAIT0();
            __syncthreads();
        }
    }

    // ---- epilogue ----
#pragma unroll
    for (int r = 0; r < 2; r++) {
        float inv = 1.f / lrow[r];
        int tok = qt*128 + w*16 + trow + r*8;
        size_t rowb = (size_t)(b*Nn + tok)*HID + h*DH;
#pragma unroll
        for (int nt = 0; nt < 8; nt++) {
            uint32_t h32, l32;
            split2(oacc[nt][2*r]*inv, oacc[nt][2*r+1]*inv, h32, l32);
            int col = nt*8 + tcol;
            *(uint32_t*)(d_ohi + rowb + col) = h32;
            *(uint32_t*)(d_olo + rowb + col) = l32;
        }
    }
}

// ------------------------- GN2 apply -> final output -------------------------
__global__ void gn_apply_kernel(float* __restrict__ out) {
    int f = blockIdx.x * 256 + threadIdx.x;
    float4 v = ((const float4*)d_y)[f];
    int bc = f / (Nn/4);
    float s = d_s2[bc], bb = d_b2[bc];
    float4 r;
    r.x = v.x*s + bb; r.y = v.y*s + bb; r.z = v.z*s + bb; r.w = v.w*s + bb;
    ((float4*)out)[f] = r;
}

// ------------------------- launch -------------------------
extern "C" void kernel_launch(void* const* d_in, const int* in_sizes, int n_in,
                              void* d_out, int out_size) {
    const float* x     = (const float*)d_in[0];
    const float* gn1_w = (const float*)d_in[1];
    const float* gn1_b = (const float*)d_in[2];
    const float* w_qkv = (const float*)d_in[3];
    const float* memkv = (const float*)d_in[4];
    const float* w_out = (const float*)d_in[5];
    const float* b_out = (const float*)d_in[6];
    const float* gn2_w = (const float*)d_in[7];
    const float* gn2_b = (const float*)d_in[8];
    float* out = (float*)d_out;

    static bool attr_set = false;
    if (!attr_set) {
        cudaFuncSetAttribute(flash_mma_kernel, cudaFuncAttributeMaxDynamicSharedMemorySize, FLASH_SMEM_BYTES);
        cudaFuncSetAttribute(qkv_mma_kernel,   cudaFuncAttributeMaxDynamicSharedMemorySize, GEMM_SMEM_BYTES);
        cudaFuncSetAttribute(out_mma_kernel,   cudaFuncAttributeMaxDynamicSharedMemorySize, GEMM_SMEM_BYTES);
        attr_set = true;
    }

    float *p_s1, *p_b1;
    cudaGetSymbolAddress((void**)&p_s1, d_s1);
    cudaGetSymbolAddress((void**)&p_b1, d_b1);

    gn_stats_kernel<<<Bb*Gg, 256>>>(x, gn1_w, gn1_b, p_s1, p_b1);
    prep_misc_kernel<<<SPLIT_TOTAL + Bb*NH*8, 256>>>(w_qkv, w_out, memkv);
    prep_x_kernel<<<dim3(Nn/32, Cc/32, Bb), 256>>>(x);
    qkv_mma_kernel<<<dim3(Nn/128, QKVJ/128, Bb), 256, GEMM_SMEM_BYTES>>>();
    flash_mma_kernel<<<dim3(Nn/128, NH, Bb), 256, FLASH_SMEM_BYTES>>>();
    out_mma_kernel<<<dim3(OUT_NX, OUT_NY, Bb), 256, GEMM_SMEM_BYTES>>>(b_out);
    gn2_finalize_kernel<<<1, 64>>>(gn2_w, gn2_b);
    gn_apply_kernel<<<(Bb*Cc*Nn/4)/256, 256>>>(out);
}